// round 9
// baseline (speedup 1.0000x reference)
#include <cuda_runtime.h>
#include <cstdint>

#define NSPAN  256
#define KKNOW  1024
#define DMODEL 512
#define LMAX   64
#define HID    500
#define NPAIR  (NSPAN * (LMAX + 1))   /* 16640 = 130 * 128 */

// ---------------- scratch (device globals; no allocation) ----------------
__device__ float g_sentinel[NSPAN * DMODEL];
__device__ float g_span_part[NSPAN * DMODEL];   // includes b1, cols [500,512)=0
__device__ float g_know_part[KKNOW * DMODEL];
__device__ float g_sent_part[NSPAN * DMODEL];
__device__ float g_W2t[DMODEL * DMODEL];        // W2^T, tf32, 4-group permuted k
__device__ float g_WsT[DMODEL * DMODEL];        // Ws^T
__device__ float g_W1aT[DMODEL * DMODEL];       // W1a^T
__device__ float g_W1bT[DMODEL * DMODEL];       // W1b^T
__device__ float g_b2p[DMODEL];
__device__ float g_w3p[DMODEL];
__device__ float g_scpart[2 * NPAIR];           // per-N-half score partials

// sense-reversing grid barriers (self-resetting across graph replays)
__device__ int g_cntA = 0, g_senseA = 0;        // fused_small: prep -> gemms (96)
__device__ int g_cntB = 0, g_senseB = 0;        // fused_small: sentinel -> sent (16)
__device__ int g_cntP = 0, g_senseP = 0;        // pair: gemm -> softmax (260)

__device__ __forceinline__ void grid_barrier(int* cnt, int* sense, int total) {
    __syncthreads();
    if (threadIdx.x == 0) {
        __threadfence();
        volatile int* vs = (volatile int*)sense;
        int target = 1 - *vs;
        int n = atomicAdd(cnt, 1);
        if (n == total - 1) {
            *cnt = 0;
            __threadfence();
            *vs = target;
        } else {
            while (*vs != target) __nanosleep(32);
        }
        __threadfence();
    }
    __syncthreads();
}

__device__ __forceinline__ uint32_t f2tf32(float x) {
    uint32_t r;
    asm("cvt.rna.tf32.f32 %0, %1;" : "=r"(r) : "f"(x));
    return r;
}
__device__ __forceinline__ uint32_t smem_u32(const void* p) {
    uint32_t a;
    asm("{ .reg .u64 t; cvta.to.shared.u64 t, %1; cvt.u32.u64 %0, t; }"
        : "=r"(a) : "l"(p));
    return a;
}
__device__ __forceinline__ void mma_tf32(float* c,
                                         uint32_t a0, uint32_t a1, uint32_t a2, uint32_t a3,
                                         uint32_t b0, uint32_t b1) {
    asm volatile(
        "mma.sync.aligned.m16n8k8.row.col.f32.tf32.tf32.f32 "
        "{%0,%1,%2,%3}, {%4,%5,%6,%7}, {%8,%9}, {%0,%1,%2,%3};"
        : "+f"(c[0]), "+f"(c[1]), "+f"(c[2]), "+f"(c[3])
        : "r"(a0), "r"(a1), "r"(a2), "r"(a3), "r"(b0), "r"(b1));
}
#define CP_ASYNC16(dst, src) \
    asm volatile("cp.async.cg.shared.global [%0], [%1], 16;" \
                 :: "r"(dst), "l"(src) : "memory")
#define CP_COMMIT() asm volatile("cp.async.commit_group;" ::: "memory")
#define CP_WAIT(n)  asm volatile("cp.async.wait_group %0;" :: "n"(n) : "memory")

// B-side 4-group permutation ((k, k+4, k+8, k+12) adjacent) — LDS.128 fragments
#define PERMB(c) ((((c) & 3) << 2) | (((c) >> 2) & 3))

// smem word layout (dynamic):
//   As: 2 bufs of 128*24 @ 0, 3072      (pair-perm, pitch 24, conflict-free)
//   Bs: 4 bufs of 128*16 @ 6144 + q*2048 (PERMB, pitch 16)
//   sred: 256 floats @ 14336
#define APITCH 24
#define SMEM_WORDS (14336 + 256)
#define SMEM_BYTES (SMEM_WORDS * 4)

// ================= unified pipelined tf32 mma GEMM core (R6/R8 shape) =======
// CTA tile 128(M) x 128(N), K=512 in 32 chunks of 16.
// 256 threads = 8 warps (4M x 2N), warp tile 32x64, acc[2][8][4].
template<bool PAIR>
__device__ __forceinline__ void gemm_core(
    int m0, int n0,
    const float* __restrict__ arp1, const float* __restrict__ arp2,
    const float* __restrict__ Bt,
    const float* __restrict__ bias, float* __restrict__ C, int N, int relu) {
    extern __shared__ uint32_t sm[];
    const int tid = threadIdx.x;
    const int lane = tid & 31, wid = tid >> 5;
    const int gid = lane >> 2, tig = lane & 3;
    const int wm = wid >> 1, wn = wid & 1;        // 4M x 2N warps
    const int arow = tid >> 1, ah = (tid & 1) * 8;

    const float* brp = Bt + (size_t)(n0 + arow) * DMODEL + ah;
    arp1 += ah;
    arp2 += ah;

    uint32_t su = smem_u32(sm);
    uint32_t bdst[4];
#pragma unroll
    for (int q = 0; q < 4; q++)
        bdst[q] = su + (uint32_t)(6144 + q * 2048 + arow * 16 + ah) * 4;

    float acc[2][8][4];
#pragma unroll
    for (int mi = 0; mi < 2; mi++)
#pragma unroll
        for (int ni = 0; ni < 8; ni++)
#pragma unroll
            for (int q = 0; q < 4; q++) acc[mi][ni][q] = 0.f;

    float4 pa1[2], pa2[2];

#define LDA(s) do { int _k = (s) * 16;                                        \
    pa1[0] = *(const float4*)(arp1 + _k);                                     \
    pa1[1] = *(const float4*)(arp1 + _k + 4);                                 \
    if (PAIR) {                                                               \
        pa2[0] = *(const float4*)(arp2 + _k);                                 \
        pa2[1] = *(const float4*)(arp2 + _k + 4);                             \
    } } while (0)

#define STA(b) do {                                                           \
    uint32_t* _d = sm + (b) * 3072 + arow * APITCH + ah;                      \
    float w0, w1, w2, w3, w4, w5, w6, w7;                                     \
    if (PAIR) {                                                               \
        w0 = fmaxf(pa1[0].x + pa2[0].x, 0.f);                                 \
        w1 = fmaxf(pa1[0].y + pa2[0].y, 0.f);                                 \
        w2 = fmaxf(pa1[0].z + pa2[0].z, 0.f);                                 \
        w3 = fmaxf(pa1[0].w + pa2[0].w, 0.f);                                 \
        w4 = fmaxf(pa1[1].x + pa2[1].x, 0.f);                                 \
        w5 = fmaxf(pa1[1].y + pa2[1].y, 0.f);                                 \
        w6 = fmaxf(pa1[1].z + pa2[1].z, 0.f);                                 \
        w7 = fmaxf(pa1[1].w + pa2[1].w, 0.f);                                 \
    } else {                                                                  \
        w0 = pa1[0].x; w1 = pa1[0].y; w2 = pa1[0].z; w3 = pa1[0].w;           \
        w4 = pa1[1].x; w5 = pa1[1].y; w6 = pa1[1].z; w7 = pa1[1].w;           \
    }                                                                         \
    uint4 q0 = make_uint4(__float_as_uint(w0), __float_as_uint(w4),           \
                          __float_as_uint(w1), __float_as_uint(w5));          \
    uint4 q1 = make_uint4(__float_as_uint(w2), __float_as_uint(w6),           \
                          __float_as_uint(w3), __float_as_uint(w7));          \
    *(uint4*)&_d[0] = q0;                                                     \
    *(uint4*)&_d[4] = q1; } while (0)

// always commits (possibly-empty group) so CP_WAIT counts stay static
#define LDB(s, q) do { if ((s) < 32) { int _k = (s) * 16;                     \
        CP_ASYNC16(bdst[q], brp + _k);                                        \
        CP_ASYNC16(bdst[q] + 16, brp + _k + 4); }                             \
    CP_COMMIT(); } while (0)

#define COMPUTE(AB, BB) do {                                                  \
    const uint32_t* A_ = sm + (AB) * 3072;                                    \
    const uint32_t* B_ = sm + 6144 + (BB) * 2048;                             \
    uint2 aa[2][2][2];                                                        \
    _Pragma("unroll") for (int ks = 0; ks < 2; ks++)                          \
    _Pragma("unroll") for (int mi = 0; mi < 2; mi++) {                        \
        int r = wm * 32 + mi * 16 + gid;                                      \
        int kko = ks * 8 + tig * 2;                                           \
        aa[ks][mi][0] = *(const uint2*)&A_[r * APITCH + kko];                 \
        aa[ks][mi][1] = *(const uint2*)&A_[(r + 8) * APITCH + kko];           \
    }                                                                         \
    _Pragma("unroll") for (int ni = 0; ni < 8; ni++) {                        \
        int nr = wn * 64 + ni * 8 + gid;                                      \
        uint4 b = *(const uint4*)&B_[nr * 16 + tig * 4];                      \
        mma_tf32(acc[0][ni], aa[0][0][0].x, aa[0][0][1].x,                    \
                 aa[0][0][0].y, aa[0][0][1].y, b.x, b.y);                     \
        mma_tf32(acc[1][ni], aa[0][1][0].x, aa[0][1][1].x,                    \
                 aa[0][1][0].y, aa[0][1][1].y, b.x, b.y);                     \
        mma_tf32(acc[0][ni], aa[1][0][0].x, aa[1][0][1].x,                    \
                 aa[1][0][0].y, aa[1][0][1].y, b.z, b.w);                     \
        mma_tf32(acc[1][ni], aa[1][1][0].x, aa[1][1][1].x,                    \
                 aa[1][1][0].y, aa[1][1][1].y, b.z, b.w);                     \
    } } while (0)

#define ITER(s, AB, BB) do {                                                  \
    if ((s) + 1 < 32) STA((AB) ^ 1);                                          \
    if ((s) + 2 < 32) LDA((s) + 2);                                           \
    LDB((s) + 3, ((BB) + 3) & 3);                                             \
    CP_WAIT(2);                                                               \
    COMPUTE(AB, BB);                                                          \
    __syncthreads(); } while (0)

    // prologue: chunk0 -> A0, B groups 0..2 in flight, chunk1 in regs
    LDA(0); STA(0);
    LDB(0, 0); LDB(1, 1); LDB(2, 2);
    LDA(1);
    CP_WAIT(2);
    __syncthreads();

#pragma unroll 1
    for (int s0 = 0; s0 < 28; s0 += 4) {
        ITER(s0 + 0, 0, 0);
        ITER(s0 + 1, 1, 1);
        ITER(s0 + 2, 0, 2);
        ITER(s0 + 3, 1, 3);
    }
    ITER(28, 0, 0);
    ITER(29, 1, 1);
    ITER(30, 0, 2);
    ITER(31, 1, 3);

#undef LDA
#undef STA
#undef LDB
#undef COMPUTE
#undef ITER

    if (PAIR) {
        // accumulate per-row score partials over this 128-col tile into sred
        float* sred = (float*)(sm + 14336);
#pragma unroll
        for (int mi = 0; mi < 2; mi++) {
            float p0 = 0.f, p1 = 0.f;
#pragma unroll
            for (int ni = 0; ni < 8; ni++) {
                int nn = n0 + wn * 64 + ni * 8 + 2 * tig;
                float b2a = g_b2p[nn],     w3a = g_w3p[nn];
                float b2b = g_b2p[nn + 1], w3b = g_w3p[nn + 1];
                p0 += fmaxf(acc[mi][ni][0] + b2a, 0.f) * w3a
                    + fmaxf(acc[mi][ni][1] + b2b, 0.f) * w3b;
                p1 += fmaxf(acc[mi][ni][2] + b2a, 0.f) * w3a
                    + fmaxf(acc[mi][ni][3] + b2b, 0.f) * w3b;
            }
            p0 += __shfl_xor_sync(0xFFFFFFFFu, p0, 1);
            p0 += __shfl_xor_sync(0xFFFFFFFFu, p0, 2);
            p1 += __shfl_xor_sync(0xFFFFFFFFu, p1, 1);
            p1 += __shfl_xor_sync(0xFFFFFFFFu, p1, 2);
            if (tig == 0) {
                int r = wm * 32 + mi * 16 + gid;
                sred[r * 2 + wn] += p0;
                sred[(r + 8) * 2 + wn] += p1;
            }
        }
        __syncthreads();
    } else {
#pragma unroll
        for (int mi = 0; mi < 2; mi++) {
            int r = m0 + wm * 32 + mi * 16 + gid;
#pragma unroll
            for (int ni = 0; ni < 8; ni++) {
                int nn = n0 + wn * 64 + ni * 8 + 2 * tig;
                float ba = (bias && nn < N) ? bias[nn] : 0.f;
                float bb = (bias && nn + 1 < N) ? bias[nn + 1] : 0.f;
                float c0 = (nn < N) ? acc[mi][ni][0] + ba : 0.f;
                float c1 = (nn + 1 < N) ? acc[mi][ni][1] + bb : 0.f;
                float c2 = (nn < N) ? acc[mi][ni][2] + ba : 0.f;
                float c3 = (nn + 1 < N) ? acc[mi][ni][3] + bb : 0.f;
                if (relu) {
                    c0 = fmaxf(c0, 0.f); c1 = fmaxf(c1, 0.f);
                    c2 = fmaxf(c2, 0.f); c3 = fmaxf(c3, 0.f);
                }
                *(float2*)&C[(size_t)r * DMODEL + nn] = make_float2(c0, c1);
                *(float2*)&C[(size_t)(r + 8) * DMODEL + nn] = make_float2(c2, c3);
            }
        }
    }
}

// ============ fused kernel 1: prep + {sentinel, span_part, know_part} + sent
// grid = 96 CTAs x 256 threads (single wave even at 1 CTA/SM: 96 <= 148).
__global__ void __launch_bounds__(256, 2) fused_small_kernel(
    const float* __restrict__ span, const float* __restrict__ know,
    const float* __restrict__ Ws, const float* __restrict__ W1,
    const float* __restrict__ W2, const float* __restrict__ bs,
    const float* __restrict__ b1, const float* __restrict__ b2,
    const float* __restrict__ W3) {
    const int bid = blockIdx.x;
    const int tid = threadIdx.x;

    // ---- prep phase: transpose+tf32+permute W2/Ws/W1a/W1b, pad b2/w3 ----
    int gtid = bid * 256 + tid;
    for (int i = gtid; i < 4 * DMODEL * DMODEL; i += 96 * 256) {
        int z = i >> 18, j = i & (DMODEL * DMODEL - 1);
        int k = j >> 9, n = j & 511;
        float v;
        float* dst;
        if (z == 0)      { v = (k < HID && n < HID) ? W2[k * HID + n] : 0.f; dst = g_W2t; }
        else if (z == 1) { v = Ws[k * DMODEL + n];                           dst = g_WsT; }
        else if (z == 2) { v = (n < HID) ? W1[k * HID + n] : 0.f;            dst = g_W1aT; }
        else             { v = (n < HID) ? W1[(k + DMODEL) * HID + n] : 0.f; dst = g_W1bT; }
        dst[n * DMODEL + (k & ~15) + PERMB(k & 15)] = __uint_as_float(f2tf32(v));
    }
    if (gtid < DMODEL) {
        g_b2p[gtid] = (gtid < HID) ? b2[gtid] : 0.f;
        g_w3p[gtid] = (gtid < HID) ? W3[gtid] : 0.f;
    }
    grid_barrier(&g_cntA, &g_senseA, 96);

    // ---- phase 1 GEMMs ----
    if (bid < 8) {                 // sentinel = relu(span @ Ws + bs)
        int x = bid & 3, y = bid >> 2;
        const float* a1 = span + (size_t)(y * 128 + (tid >> 1)) * DMODEL;
        gemm_core<false>(y * 128, x * 128, a1, a1, g_WsT, bs, g_sentinel, DMODEL, 1);
        grid_barrier(&g_cntB, &g_senseB, 16);      // release sent-phase CTAs
    } else if (bid < 16) {         // span_part = span @ W1a + b1
        int q = bid - 8;
        int x = q & 3, y = q >> 2;
        const float* a1 = span + (size_t)(y * 128 + (tid >> 1)) * DMODEL;
        gemm_core<false>(y * 128, x * 128, a1, a1, g_W1aT, b1, g_span_part, HID, 0);
    } else if (bid < 48) {         // know_part = know @ W1b
        int q = bid - 16;
        int x = q & 3, y = q >> 2;
        const float* a1 = know + (size_t)(y * 128 + (tid >> 1)) * DMODEL;
        gemm_core<false>(y * 128, x * 128, a1, a1, g_W1bT, nullptr, g_know_part, HID, 0);
    } else if (bid < 56) {         // sent_part = sentinel @ W1b (waits on sentinel only)
        grid_barrier(&g_cntB, &g_senseB, 16);
        int q = bid - 48;
        int x = q & 3, y = q >> 2;
        const float* a1 = g_sentinel + (size_t)(y * 128 + (tid >> 1)) * DMODEL;
        gemm_core<false>(y * 128, x * 128, a1, a1, g_W1bT, nullptr, g_sent_part, HID, 0);
    }
}

// ============ fused kernel 2: pair GEMM + grid barrier + softmax/features ==
// grid (2, 130) = 260 CTAs; __launch_bounds__(256,2) guarantees co-residency
// (260 <= 2*148).
__global__ void __launch_bounds__(256, 2) pair_mma_kernel(
    const int* __restrict__ s2c, const int* __restrict__ lengths,
    const float* __restrict__ know, float* __restrict__ out) {
    extern __shared__ uint32_t sm[];
    int m0 = blockIdx.y * 128;
    int row = threadIdx.x >> 1;
    int p = m0 + row, nsp = p / 65, l = p - nsp * 65;
    const float* a1 = g_span_part + (size_t)nsp * DMODEL;
    const float* a2 = (l < LMAX)
        ? g_know_part + (size_t)s2c[nsp * LMAX + l] * DMODEL
        : g_sent_part + (size_t)nsp * DMODEL;

    float* sred = (float*)(sm + 14336);
    sred[threadIdx.x] = 0.f;             // zero partial accumulators
    int n0 = blockIdx.x * 256;
    gemm_core<true>(m0, n0,       a1, a2, g_W2t, nullptr, nullptr, 0, 0);
    gemm_core<true>(m0, n0 + 128, a1, a2, g_W2t, nullptr, nullptr, 0, 0);
    if (threadIdx.x < 128)
        g_scpart[blockIdx.x * NPAIR + m0 + threadIdx.x] =
            sred[threadIdx.x * 2] + sred[threadIdx.x * 2 + 1];

    // ---- grid-wide barrier, then softmax + feature aggregation ----
    grid_barrier(&g_cntP, &g_senseP, 260);

    int bid = blockIdx.y * 2 + blockIdx.x;
    if (bid >= NSPAN) return;
    int n = bid;
    int t = threadIdx.x;
    float* sc = (float*)sm;                              // 65 floats @ word 0
    const float** eptr = (const float**)(sm + 68);       // 65 ptrs  @ word 68

    if (t < 65) {
        float s = __ldcg(&g_scpart[n * 65 + t]) + __ldcg(&g_scpart[NPAIR + n * 65 + t]);
        bool valid;
        const float* ep;
        if (t < LMAX) {
            int len = lengths[n];
            if (len < 1) len = 1;
            valid = t < len;
            ep = know + (size_t)s2c[n * LMAX + t] * DMODEL;
        } else {
            valid = true;
            ep = g_sentinel + (size_t)n * DMODEL;
        }
        sc[t] = valid ? s : -1e30f;
        eptr[t] = ep;
    }
    __syncthreads();
    if (t == 0) {
        float m = sc[0];
        for (int i = 1; i < 65; i++) m = fmaxf(m, sc[i]);
        float ssum = 0.f;
        for (int i = 0; i < 65; i++) { float e = expf(sc[i] - m); sc[i] = e; ssum += e; }
        float inv = 1.f / ssum;
        for (int i = 0; i < 65; i++) sc[i] *= inv;
    }
    __syncthreads();
    if (t < 65)
        out[NSPAN * DMODEL + n * 65 + t] = sc[t];        // probs

    float a0 = 0.f, acc1 = 0.f;                          // cols t and t+256
#pragma unroll 1
    for (int i = 0; i < 65; i++) {
        float pr = sc[i];
        const float* ep = eptr[i];
        a0   += pr * ep[t];
        acc1 += pr * ep[t + 256];
    }
    out[n * DMODEL + t]       = a0;                      // features
    out[n * DMODEL + t + 256] = acc1;
}

// ---------------- launch ----------------
extern "C" void kernel_launch(void* const* d_in, const int* in_sizes, int n_in,
                              void* d_out, int out_size) {
    const float* span    = (const float*)d_in[0];
    const float* know    = (const float*)d_in[1];
    const int*   s2c     = (const int*)d_in[2];
    const int*   lengths = (const int*)d_in[3];
    const float* Ws      = (const float*)d_in[4];
    const float* bs      = (const float*)d_in[5];
    const float* W1      = (const float*)d_in[6];
    const float* b1      = (const float*)d_in[7];
    const float* W2      = (const float*)d_in[8];
    const float* b2      = (const float*)d_in[9];
    const float* W3      = (const float*)d_in[10];
    // d_in[11] = b3: softmax-invariant constant shift, intentionally unused.
    float* out = (float*)d_out;

    cudaFuncSetAttribute(fused_small_kernel,
                         cudaFuncAttributeMaxDynamicSharedMemorySize, SMEM_BYTES);
    cudaFuncSetAttribute(pair_mma_kernel,
                         cudaFuncAttributeMaxDynamicSharedMemorySize, SMEM_BYTES);

    // prep + sentinel + span_part + know_part + sent_part (one launch)
    fused_small_kernel<<<96, 256, SMEM_BYTES>>>(
        span, know, Ws, W1, W2, bs, b1, b2, W3);
    // pair GEMM -> scores -> softmax + features (one launch)
    pair_mma_kernel<<<dim3(2, 130), 256, SMEM_BYTES>>>(s2c, lengths, know, out);
}

// round 10
// speedup vs baseline: 1.4205x; 1.4205x over previous
#include <cuda_runtime.h>
#include <cstdint>

#define NSPAN  256
#define KKNOW  1024
#define DMODEL 512
#define LMAX   64
#define HID    500
#define NPAIR  (NSPAN * (LMAX + 1))   /* 16640 = 130 * 128 */

// ---------------- scratch (device globals; no allocation) ----------------
__device__ float g_sentinel[NSPAN * DMODEL];
__device__ float g_span_part[NSPAN * DMODEL];   // includes b1, cols [500,512)=0
__device__ float g_know_part[KKNOW * DMODEL];
__device__ float g_sent_part[NSPAN * DMODEL];
__device__ uint32_t g_W2b[DMODEL * 256];        // W2^T bf16x2, word-permuted
__device__ float g_WsT[DMODEL * DMODEL];        // Ws^T, tf32, PERMB
__device__ float g_W1aT[DMODEL * DMODEL];       // W1a^T
__device__ float g_W1bT[DMODEL * DMODEL];       // W1b^T
__device__ float g_b2p[DMODEL];
__device__ float g_w3p[DMODEL];
__device__ float g_scpart[4 * NPAIR];           // per-N-tile score partials

__device__ __forceinline__ uint32_t f2tf32(float x) {
    uint32_t r;
    asm("cvt.rna.tf32.f32 %0, %1;" : "=r"(r) : "f"(x));
    return r;
}
__device__ __forceinline__ uint32_t packbf(float lo, float hi) {
    uint32_t r;
    asm("cvt.rn.bf16x2.f32 %0, %1, %2;" : "=r"(r) : "f"(hi), "f"(lo));
    return r;
}
__device__ __forceinline__ uint32_t smem_u32(const void* p) {
    uint32_t a;
    asm("{ .reg .u64 t; cvta.to.shared.u64 t, %1; cvt.u32.u64 %0, t; }"
        : "=r"(a) : "l"(p));
    return a;
}
__device__ __forceinline__ void mma_tf32(float* c,
                                         uint32_t a0, uint32_t a1, uint32_t a2, uint32_t a3,
                                         uint32_t b0, uint32_t b1) {
    asm volatile(
        "mma.sync.aligned.m16n8k8.row.col.f32.tf32.tf32.f32 "
        "{%0,%1,%2,%3}, {%4,%5,%6,%7}, {%8,%9}, {%0,%1,%2,%3};"
        : "+f"(c[0]), "+f"(c[1]), "+f"(c[2]), "+f"(c[3])
        : "r"(a0), "r"(a1), "r"(a2), "r"(a3), "r"(b0), "r"(b1));
}
__device__ __forceinline__ void mma_bf16(float* c,
                                         uint32_t a0, uint32_t a1, uint32_t a2, uint32_t a3,
                                         uint32_t b0, uint32_t b1) {
    asm volatile(
        "mma.sync.aligned.m16n8k16.row.col.f32.bf16.bf16.f32 "
        "{%0,%1,%2,%3}, {%4,%5,%6,%7}, {%8,%9}, {%0,%1,%2,%3};"
        : "+f"(c[0]), "+f"(c[1]), "+f"(c[2]), "+f"(c[3])
        : "r"(a0), "r"(a1), "r"(a2), "r"(a3), "r"(b0), "r"(b1));
}
#define CP_ASYNC16(dst, src) \
    asm volatile("cp.async.cg.shared.global [%0], [%1], 16;" \
                 :: "r"(dst), "l"(src) : "memory")
#define CP_COMMIT() asm volatile("cp.async.commit_group;" ::: "memory")
#define CP_WAIT(n)  asm volatile("cp.async.wait_group %0;" :: "n"(n) : "memory")

// fp32 B-side 4-group permutation (tf32 core): LDS.128 fragments
#define PERMB(c) ((((c) & 3) << 2) | (((c) >> 2) & 3))
// bf16 word-pair permutation: (word w, w+4) adjacent -> LDS.64 fragments
#define PERMW(w) ((((w) & 3) << 1) | (((w) >> 2) & 1))

// ---- tf32 small-GEMM smem layout (words) ----
#define APITCH 24
#define SMEM_SMALL_WORDS (6144 + 4 * 2048)
#define SMEM_SMALL_BYTES (SMEM_SMALL_WORDS * 4)
// ---- bf16 pair-GEMM smem layout (words): A 2x1024 @0, B 4x1024 @2048, sred @6144
#define SMEM_PAIR_BYTES ((6144 + 256) * 4)

// ---------------- prep: W2 -> bf16 permuted; Ws/W1a/W1b -> tf32 permuted ---
__global__ void prep_kernel(const float* __restrict__ W2,
                            const float* __restrict__ Ws,
                            const float* __restrict__ W1,
                            const float* __restrict__ b2,
                            const float* __restrict__ W3) {
    int i = blockIdx.x * blockDim.x + threadIdx.x;   // 0 .. 512*512-1
    int z = blockIdx.y;
    if (z == 0) {
        if (i < DMODEL * 256) {                      // bf16 words
            int n = i >> 8, g = i & 255;
            int k = g * 2;
            float v0 = (k < HID && n < HID) ? W2[k * HID + n] : 0.f;
            float v1 = (k + 1 < HID && n < HID) ? W2[(k + 1) * HID + n] : 0.f;
            g_W2b[n * 256 + (g & ~7) + PERMW(g & 7)] = packbf(v0, v1);
        }
        if (i < DMODEL) {
            g_b2p[i] = (i < HID) ? b2[i] : 0.f;
            g_w3p[i] = (i < HID) ? W3[i] : 0.f;
        }
        return;
    }
    int k = i >> 9, n = i & 511;
    float v;
    float* dst;
    if (z == 1)      { v = Ws[k * DMODEL + n];                           dst = g_WsT; }
    else if (z == 2) { v = (n < HID) ? W1[k * HID + n] : 0.f;            dst = g_W1aT; }
    else             { v = (n < HID) ? W1[(k + DMODEL) * HID + n] : 0.f; dst = g_W1bT; }
    dst[n * DMODEL + (k & ~15) + PERMB(k & 15)] = __uint_as_float(f2tf32(v));
}

// ================= tf32 pipelined GEMM core (R6 shape, smalls only) ========
__device__ __forceinline__ void gemm_core_f32(
    int m0, int n0, const float* __restrict__ arp1, const float* __restrict__ Bt,
    const float* __restrict__ bias, float* __restrict__ C, int N, int relu) {
    extern __shared__ uint32_t sm[];
    const int tid = threadIdx.x;
    const int lane = tid & 31, wid = tid >> 5;
    const int gid = lane >> 2, tig = lane & 3;
    const int wm = wid >> 1, wn = wid & 1;        // 4M x 2N warps
    const int arow = tid >> 1, ah = (tid & 1) * 8;

    const float* brp = Bt + (size_t)(n0 + arow) * DMODEL + ah;
    arp1 += ah;

    uint32_t su = smem_u32(sm);
    uint32_t bdst[4];
#pragma unroll
    for (int q = 0; q < 4; q++)
        bdst[q] = su + (uint32_t)(6144 + q * 2048 + arow * 16 + ah) * 4;

    float acc[2][8][4];
#pragma unroll
    for (int mi = 0; mi < 2; mi++)
#pragma unroll
        for (int ni = 0; ni < 8; ni++)
#pragma unroll
            for (int q = 0; q < 4; q++) acc[mi][ni][q] = 0.f;

    float4 pa1[2];

#define LDA(s) do { int _k = (s) * 16;                                        \
    pa1[0] = *(const float4*)(arp1 + _k);                                     \
    pa1[1] = *(const float4*)(arp1 + _k + 4); } while (0)

#define STA(b) do {                                                           \
    uint32_t* _d = sm + (b) * 3072 + arow * APITCH + ah;                      \
    uint4 q0 = make_uint4(__float_as_uint(pa1[0].x), __float_as_uint(pa1[1].x),\
                          __float_as_uint(pa1[0].y), __float_as_uint(pa1[1].y));\
    uint4 q1 = make_uint4(__float_as_uint(pa1[0].z), __float_as_uint(pa1[1].z),\
                          __float_as_uint(pa1[0].w), __float_as_uint(pa1[1].w));\
    *(uint4*)&_d[0] = q0;                                                     \
    *(uint4*)&_d[4] = q1; } while (0)

#define LDB(s, q) do { if ((s) < 32) { int _k = (s) * 16;                     \
        CP_ASYNC16(bdst[q], brp + _k);                                        \
        CP_ASYNC16(bdst[q] + 16, brp + _k + 4); }                             \
    CP_COMMIT(); } while (0)

#define COMPUTE(AB, BB) do {                                                  \
    const uint32_t* A_ = sm + (AB) * 3072;                                    \
    const uint32_t* B_ = sm + 6144 + (BB) * 2048;                             \
    uint2 aa[2][2][2];                                                        \
    _Pragma("unroll") for (int ks = 0; ks < 2; ks++)                          \
    _Pragma("unroll") for (int mi = 0; mi < 2; mi++) {                        \
        int r = wm * 32 + mi * 16 + gid;                                      \
        int kko = ks * 8 + tig * 2;                                           \
        aa[ks][mi][0] = *(const uint2*)&A_[r * APITCH + kko];                 \
        aa[ks][mi][1] = *(const uint2*)&A_[(r + 8) * APITCH + kko];           \
    }                                                                         \
    _Pragma("unroll") for (int ni = 0; ni < 8; ni++) {                        \
        int nr = wn * 64 + ni * 8 + gid;                                      \
        uint4 b = *(const uint4*)&B_[nr * 16 + tig * 4];                      \
        mma_tf32(acc[0][ni], aa[0][0][0].x, aa[0][0][1].x,                    \
                 aa[0][0][0].y, aa[0][0][1].y, b.x, b.y);                     \
        mma_tf32(acc[1][ni], aa[0][1][0].x, aa[0][1][1].x,                    \
                 aa[0][1][0].y, aa[0][1][1].y, b.x, b.y);                     \
        mma_tf32(acc[0][ni], aa[1][0][0].x, aa[1][0][1].x,                    \
                 aa[1][0][0].y, aa[1][0][1].y, b.z, b.w);                     \
        mma_tf32(acc[1][ni], aa[1][1][0].x, aa[1][1][1].x,                    \
                 aa[1][1][0].y, aa[1][1][1].y, b.z, b.w);                     \
    } } while (0)

#define ITER(s, AB, BB) do {                                                  \
    if ((s) + 1 < 32) STA((AB) ^ 1);                                          \
    if ((s) + 2 < 32) LDA((s) + 2);                                           \
    LDB((s) + 3, ((BB) + 3) & 3);                                             \
    CP_WAIT(2);                                                               \
    COMPUTE(AB, BB);                                                          \
    __syncthreads(); } while (0)

    LDA(0); STA(0);
    LDB(0, 0); LDB(1, 1); LDB(2, 2);
    LDA(1);
    CP_WAIT(2);
    __syncthreads();

#pragma unroll 1
    for (int s0 = 0; s0 < 28; s0 += 4) {
        ITER(s0 + 0, 0, 0);
        ITER(s0 + 1, 1, 1);
        ITER(s0 + 2, 0, 2);
        ITER(s0 + 3, 1, 3);
    }
    ITER(28, 0, 0);
    ITER(29, 1, 1);
    ITER(30, 0, 2);
    ITER(31, 1, 3);

#undef LDA
#undef STA
#undef LDB
#undef COMPUTE
#undef ITER

#pragma unroll
    for (int mi = 0; mi < 2; mi++) {
        int r = m0 + wm * 32 + mi * 16 + gid;
#pragma unroll
        for (int ni = 0; ni < 8; ni++) {
            int nn = n0 + wn * 64 + ni * 8 + 2 * tig;
            float ba = (bias && nn < N) ? bias[nn] : 0.f;
            float bb = (bias && nn + 1 < N) ? bias[nn + 1] : 0.f;
            float c0 = (nn < N) ? acc[mi][ni][0] + ba : 0.f;
            float c1 = (nn + 1 < N) ? acc[mi][ni][1] + bb : 0.f;
            float c2 = (nn < N) ? acc[mi][ni][2] + ba : 0.f;
            float c3 = (nn + 1 < N) ? acc[mi][ni][3] + bb : 0.f;
            if (relu) {
                c0 = fmaxf(c0, 0.f); c1 = fmaxf(c1, 0.f);
                c2 = fmaxf(c2, 0.f); c3 = fmaxf(c3, 0.f);
            }
            *(float2*)&C[(size_t)r * DMODEL + nn] = make_float2(c0, c1);
            *(float2*)&C[(size_t)(r + 8) * DMODEL + nn] = make_float2(c2, c3);
        }
    }
}

// ================= bf16 pipelined pair GEMM =================
// CTA 128(M) x 128(N), K=512 in 32 chunks of 16. 8 warps (4M x 2N), 32x64.
// A: fp32 gather+relu -> bf16x2 permuted smem. B: bf16 cp.async (pre-permuted).
__global__ void __launch_bounds__(256, 2) pair_mma_kernel(const int* __restrict__ s2c) {
    extern __shared__ uint32_t sm[];
    const int tid = threadIdx.x;
    const int lane = tid & 31, wid = tid >> 5;
    const int gid = lane >> 2, tig = lane & 3;
    const int wm = wid >> 1, wn = wid & 1;
    const int m0 = blockIdx.y * 128, n0 = blockIdx.x * 128;
    const int row = tid >> 1, ah = tid & 1;

    int p = m0 + row, nsp = p / 65, l = p - nsp * 65;
    const float* arp1 = g_span_part + (size_t)nsp * DMODEL + ah * 4;
    const float* arp2 = ((l < LMAX)
        ? g_know_part + (size_t)s2c[nsp * LMAX + l] * DMODEL
        : g_sent_part + (size_t)nsp * DMODEL) + ah * 4;
    const char* brp = (const char*)g_W2b + (size_t)(n0 + row) * 1024 + ah * 16;

    uint32_t su = smem_u32(sm);
    uint32_t bdst[4];
#pragma unroll
    for (int q = 0; q < 4; q++)
        bdst[q] = su + (uint32_t)(2048 + q * 1024 + row * 8 + ah * 4) * 4;

    float acc[2][8][4];
#pragma unroll
    for (int mi = 0; mi < 2; mi++)
#pragma unroll
        for (int ni = 0; ni < 8; ni++)
#pragma unroll
            for (int q = 0; q < 4; q++) acc[mi][ni][q] = 0.f;

    float4 pa1[2], pa2[2];

#define LDA(s) do { int _k = (s) * 16;                                        \
    pa1[0] = *(const float4*)(arp1 + _k);                                     \
    pa1[1] = *(const float4*)(arp1 + _k + 8);                                 \
    pa2[0] = *(const float4*)(arp2 + _k);                                     \
    pa2[1] = *(const float4*)(arp2 + _k + 8); } while (0)

#define STA(b) do {                                                           \
    float f0 = fmaxf(pa1[0].x + pa2[0].x, 0.f);                               \
    float f1 = fmaxf(pa1[0].y + pa2[0].y, 0.f);                               \
    float f2 = fmaxf(pa1[0].z + pa2[0].z, 0.f);                               \
    float f3 = fmaxf(pa1[0].w + pa2[0].w, 0.f);                               \
    float f4 = fmaxf(pa1[1].x + pa2[1].x, 0.f);                               \
    float f5 = fmaxf(pa1[1].y + pa2[1].y, 0.f);                               \
    float f6 = fmaxf(pa1[1].z + pa2[1].z, 0.f);                               \
    float f7 = fmaxf(pa1[1].w + pa2[1].w, 0.f);                               \
    uint4 q = make_uint4(packbf(f0, f1), packbf(f4, f5),                      \
                         packbf(f2, f3), packbf(f6, f7));                     \
    *(uint4*)&sm[(b) * 1024 + row * 8 + ah * 4] = q; } while (0)

#define LDB(s, q) do { if ((s) < 32)                                          \
        CP_ASYNC16(bdst[q], brp + (s) * 32);                                  \
    CP_COMMIT(); } while (0)

#define COMPUTE(AB, BB) do {                                                  \
    const uint32_t* A_ = sm + (AB) * 1024;                                    \
    const uint32_t* B_ = sm + 2048 + (BB) * 1024;                             \
    uint2 bfr[8];                                                             \
    _Pragma("unroll") for (int ni = 0; ni < 8; ni++) {                        \
        int nr = wn * 64 + ni * 8 + gid;                                      \
        bfr[ni] = *(const uint2*)&B_[nr * 8 + tig * 2];                       \
    }                                                                         \
    _Pragma("unroll") for (int mi = 0; mi < 2; mi++) {                        \
        int r = wm * 32 + mi * 16 + gid;                                      \
        uint2 u0 = *(const uint2*)&A_[r * 8 + tig * 2];                       \
        uint2 u1 = *(const uint2*)&A_[(r + 8) * 8 + tig * 2];                 \
        _Pragma("unroll") for (int ni = 0; ni < 8; ni++)                      \
            mma_bf16(acc[mi][ni], u0.x, u1.x, u0.y, u1.y,                     \
                     bfr[ni].x, bfr[ni].y);                                   \
    } } while (0)

#define ITER(s, AB, BB) do {                                                  \
    if ((s) + 1 < 32) STA((AB) ^ 1);                                          \
    if ((s) + 2 < 32) LDA((s) + 2);                                           \
    LDB((s) + 3, ((BB) + 3) & 3);                                             \
    CP_WAIT(2);                                                               \
    COMPUTE(AB, BB);                                                          \
    __syncthreads(); } while (0)

    LDA(0); STA(0);
    LDB(0, 0); LDB(1, 1); LDB(2, 2);
    LDA(1);
    CP_WAIT(2);
    __syncthreads();

#pragma unroll 1
    for (int s0 = 0; s0 < 28; s0 += 4) {
        ITER(s0 + 0, 0, 0);
        ITER(s0 + 1, 1, 1);
        ITER(s0 + 2, 0, 2);
        ITER(s0 + 3, 1, 3);
    }
    ITER(28, 0, 0);
    ITER(29, 1, 1);
    ITER(30, 0, 2);
    ITER(31, 1, 3);

#undef LDA
#undef STA
#undef LDB
#undef COMPUTE
#undef ITER

    // epilogue: per-row partial score over this CTA's 128 cols
    float* sred = (float*)(sm + 6144);
#pragma unroll
    for (int mi = 0; mi < 2; mi++) {
        float p0 = 0.f, p1 = 0.f;
#pragma unroll
        for (int ni = 0; ni < 8; ni++) {
            int nn = n0 + wn * 64 + ni * 8 + 2 * tig;
            float b2a = g_b2p[nn],     w3a = g_w3p[nn];
            float b2b = g_b2p[nn + 1], w3b = g_w3p[nn + 1];
            p0 += fmaxf(acc[mi][ni][0] + b2a, 0.f) * w3a
                + fmaxf(acc[mi][ni][1] + b2b, 0.f) * w3b;
            p1 += fmaxf(acc[mi][ni][2] + b2a, 0.f) * w3a
                + fmaxf(acc[mi][ni][3] + b2b, 0.f) * w3b;
        }
        p0 += __shfl_xor_sync(0xFFFFFFFFu, p0, 1);
        p0 += __shfl_xor_sync(0xFFFFFFFFu, p0, 2);
        p1 += __shfl_xor_sync(0xFFFFFFFFu, p1, 1);
        p1 += __shfl_xor_sync(0xFFFFFFFFu, p1, 2);
        if (tig == 0) {
            int r = wm * 32 + mi * 16 + gid;
            sred[r * 2 + wn] = p0;
            sred[(r + 8) * 2 + wn] = p1;
        }
    }
    __syncthreads();
    if (tid < 128)
        g_scpart[blockIdx.x * NPAIR + m0 + tid] = sred[tid * 2] + sred[tid * 2 + 1];
}

// ---------------- small-GEMM wrappers ----------------
__global__ void __launch_bounds__(256, 2) small_multi_kernel(
    const float* __restrict__ span, const float* __restrict__ know,
    const float* __restrict__ bs, const float* __restrict__ b1) {
    int z = blockIdx.z;
    if (z < 2 && blockIdx.y >= 2) return;
    const float* A; const float* Bt; const float* bias; float* C; int N; int relu;
    if (z == 0)      { A = span; Bt = g_WsT;  bias = bs;      C = g_sentinel;  N = DMODEL; relu = 1; }
    else if (z == 1) { A = span; Bt = g_W1aT; bias = b1;      C = g_span_part; N = HID;    relu = 0; }
    else             { A = know; Bt = g_W1bT; bias = nullptr; C = g_know_part; N = HID;    relu = 0; }
    int m0 = blockIdx.y * 128;
    const float* a1 = A + (size_t)(m0 + (threadIdx.x >> 1)) * DMODEL;
    gemm_core_f32(m0, blockIdx.x * 128, a1, Bt, bias, C, N, relu);
}

__global__ void __launch_bounds__(256, 2) small_sent_kernel() {
    int m0 = blockIdx.y * 128;
    const float* a1 = g_sentinel + (size_t)(m0 + (threadIdx.x >> 1)) * DMODEL;
    gemm_core_f32(m0, blockIdx.x * 128, a1, g_W1bT, nullptr, g_sent_part, HID, 0);
}

// ---------------- softmax + feature aggregation ----------------
__global__ void __launch_bounds__(128) softmax_features_kernel(
    const int* __restrict__ s2c, const int* __restrict__ lengths,
    const float* __restrict__ know, float* __restrict__ out) {
    int n = blockIdx.x;
    int t = threadIdx.x;
    __shared__ float sc[65];
    __shared__ const float* eptr[65];
    __shared__ float redmax, redinv;

    if (t < 65) {
        float s = 0.f;
#pragma unroll
        for (int q = 0; q < 4; q++) s += g_scpart[q * NPAIR + n * 65 + t];
        bool valid;
        const float* ep;
        if (t < LMAX) {
            int len = lengths[n];
            if (len < 1) len = 1;
            valid = t < len;
            ep = know + (size_t)s2c[n * LMAX + t] * DMODEL;
        } else {
            valid = true;
            ep = g_sentinel + (size_t)n * DMODEL;
        }
        sc[t] = valid ? s : -1e30f;
        eptr[t] = ep;
    }
    __syncthreads();
    if (t == 0) {
        float m = sc[0];
        for (int l = 1; l < 65; l++) m = fmaxf(m, sc[l]);
        redmax = m;
    }
    __syncthreads();
    float m = redmax;
    if (t < 65) sc[t] = expf(sc[t] - m);
    __syncthreads();
    if (t == 0) {
        float s = 0.f;
        for (int l = 0; l < 65; l++) s += sc[l];
        redinv = 1.f / s;
    }
    __syncthreads();
    if (t < 65) {
        sc[t] *= redinv;
        out[NSPAN * DMODEL + n * 65 + t] = sc[t];   // probs
    }
    __syncthreads();
    float a0 = 0.f, a1 = 0.f, a2 = 0.f, a3 = 0.f;
    for (int l = 0; l < 65; l++) {
        float pr = sc[l];
        const float* ep = eptr[l];
        a0 += pr * ep[t];
        a1 += pr * ep[t + 128];
        a2 += pr * ep[t + 256];
        a3 += pr * ep[t + 384];
    }
    out[n * DMODEL + t]       = a0;   // features
    out[n * DMODEL + t + 128] = a1;
    out[n * DMODEL + t + 256] = a2;
    out[n * DMODEL + t + 384] = a3;
}

// ---------------- launch ----------------
extern "C" void kernel_launch(void* const* d_in, const int* in_sizes, int n_in,
                              void* d_out, int out_size) {
    const float* span    = (const float*)d_in[0];
    const float* know    = (const float*)d_in[1];
    const int*   s2c     = (const int*)d_in[2];
    const int*   lengths = (const int*)d_in[3];
    const float* Ws      = (const float*)d_in[4];
    const float* bs      = (const float*)d_in[5];
    const float* W1      = (const float*)d_in[6];
    const float* b1      = (const float*)d_in[7];
    const float* W2      = (const float*)d_in[8];
    const float* b2      = (const float*)d_in[9];
    const float* W3      = (const float*)d_in[10];
    // d_in[11] = b3: softmax-invariant constant shift, intentionally unused.
    float* out = (float*)d_out;

    cudaFuncSetAttribute(small_multi_kernel,
                         cudaFuncAttributeMaxDynamicSharedMemorySize, SMEM_SMALL_BYTES);
    cudaFuncSetAttribute(small_sent_kernel,
                         cudaFuncAttributeMaxDynamicSharedMemorySize, SMEM_SMALL_BYTES);
    cudaFuncSetAttribute(pair_mma_kernel,
                         cudaFuncAttributeMaxDynamicSharedMemorySize, SMEM_PAIR_BYTES);

    // W2 -> bf16 permuted; Ws/W1a/W1b -> tf32 permuted; pad b2/w3
    prep_kernel<<<dim3(1024, 4), 256>>>(W2, Ws, W1, b2, W3);
    // sentinel / span_part / know_part concurrently (tf32)
    small_multi_kernel<<<dim3(4, 8, 3), 256, SMEM_SMALL_BYTES>>>(span, know, bs, b1);
    // sent_part = sentinel @ W1b (tf32)
    small_sent_kernel<<<dim3(4, 2), 256, SMEM_SMALL_BYTES>>>();
    // fused h1 -> h2 -> score partials (bf16 m16n8k16)
    pair_mma_kernel<<<dim3(4, 130), 256, SMEM_PAIR_BYTES>>>(s2c);
    // softmax + features
    softmax_features_kernel<<<NSPAN, 128>>>(s2c, lengths, know, out);
}

// round 11
// speedup vs baseline: 1.6218x; 1.1418x over previous
#include <cuda_runtime.h>
#include <cstdint>

#define NSPAN  256
#define KKNOW  1024
#define DMODEL 512
#define LMAX   64
#define HID    500
#define NPAIR  (NSPAN * (LMAX + 1))   /* 16640 = 130 * 128 */

// ---------------- scratch (device globals; no allocation) ----------------
__device__ float g_sentinel[NSPAN * DMODEL];
__device__ float g_span_part[NSPAN * DMODEL];   // includes b1, cols [500,512)=0
__device__ float g_know_part[KKNOW * DMODEL];
__device__ float g_sent_part[NSPAN * DMODEL];
__device__ uint32_t g_W2b[DMODEL * 256];        // W2^T  bf16x2, word-permuted
__device__ uint32_t g_Wsb[DMODEL * 256];        // Ws^T  bf16x2
__device__ uint32_t g_W1ab[DMODEL * 256];       // W1a^T bf16x2
__device__ uint32_t g_W1bb[DMODEL * 256];       // W1b^T bf16x2
__device__ float g_b2p[DMODEL];
__device__ float g_w3p[DMODEL];
__device__ float g_scpart[4 * NPAIR];           // per-N-tile score partials

__device__ __forceinline__ uint32_t packbf(float lo, float hi) {
    uint32_t r;
    asm("cvt.rn.bf16x2.f32 %0, %1, %2;" : "=r"(r) : "f"(hi), "f"(lo));
    return r;
}
__device__ __forceinline__ uint32_t smem_u32(const void* p) {
    uint32_t a;
    asm("{ .reg .u64 t; cvta.to.shared.u64 t, %1; cvt.u32.u64 %0, t; }"
        : "=r"(a) : "l"(p));
    return a;
}
__device__ __forceinline__ void mma_bf16(float* c,
                                         uint32_t a0, uint32_t a1, uint32_t a2, uint32_t a3,
                                         uint32_t b0, uint32_t b1) {
    asm volatile(
        "mma.sync.aligned.m16n8k16.row.col.f32.bf16.bf16.f32 "
        "{%0,%1,%2,%3}, {%4,%5,%6,%7}, {%8,%9}, {%0,%1,%2,%3};"
        : "+f"(c[0]), "+f"(c[1]), "+f"(c[2]), "+f"(c[3])
        : "r"(a0), "r"(a1), "r"(a2), "r"(a3), "r"(b0), "r"(b1));
}
#define CP_ASYNC16(dst, src) \
    asm volatile("cp.async.cg.shared.global [%0], [%1], 16;" \
                 :: "r"(dst), "l"(src) : "memory")
#define CP_COMMIT() asm volatile("cp.async.commit_group;" ::: "memory")
#define CP_WAIT(n)  asm volatile("cp.async.wait_group %0;" :: "n"(n) : "memory")

// bf16 word-pair permutation: (word w, w+4) adjacent -> LDS.64 fragments
#define PERMW(w) ((((w) & 3) << 1) | (((w) >> 2) & 1))

// smem layout (words): A 2x1024 @0, B 4x1024 @2048, sred/scratch 256 @6144
#define SMEM_BYTES ((6144 + 256) * 4)

// ---------------- prep: all weights -> bf16x2 permuted words; pad b2/w3 ----
__global__ void prep_kernel(const float* __restrict__ W2,
                            const float* __restrict__ Ws,
                            const float* __restrict__ W1,
                            const float* __restrict__ b2,
                            const float* __restrict__ W3) {
    int i = blockIdx.x * blockDim.x + threadIdx.x;   // 0 .. 512*256-1 (words)
    int z = blockIdx.y;
    int n = i >> 8, g = i & 255;
    int k = g * 2;
    float v0, v1;
    uint32_t* dst;
    if (z == 0) {
        v0 = (k < HID && n < HID) ? W2[k * HID + n] : 0.f;
        v1 = (k + 1 < HID && n < HID) ? W2[(k + 1) * HID + n] : 0.f;
        dst = g_W2b;
        if (i < DMODEL) {
            g_b2p[i] = (i < HID) ? b2[i] : 0.f;
            g_w3p[i] = (i < HID) ? W3[i] : 0.f;
        }
    } else if (z == 1) {
        v0 = Ws[k * DMODEL + n];
        v1 = Ws[(k + 1) * DMODEL + n];
        dst = g_Wsb;
    } else if (z == 2) {
        v0 = (n < HID) ? W1[k * HID + n] : 0.f;
        v1 = (n < HID) ? W1[(k + 1) * HID + n] : 0.f;
        dst = g_W1ab;
    } else {
        v0 = (n < HID) ? W1[(k + DMODEL) * HID + n] : 0.f;
        v1 = (n < HID) ? W1[(k + 1 + DMODEL) * HID + n] : 0.f;
        dst = g_W1bb;
    }
    dst[n * 256 + (g & ~7) + PERMW(g & 7)] = packbf(v0, v1);
}

// ================= unified bf16 pipelined GEMM core =================
// CTA 128(M) x 128(N), K=512 in 32 chunks of 16. 8 warps (4M x 2N), 32x64.
// A: fp32 loads (+add/relu for PAIR) -> bf16x2 permuted smem (2 bufs).
// B: bf16 cp.async from pre-permuted global (4 bufs, static indices).
// PAIR: epilogue folds relu(acc+b2)*w3 -> score partials.
// else: epilogue writes fp32 C with optional bias/relu (cols>=N forced 0).
template<bool PAIR>
__device__ __forceinline__ void gemm_core_bf16(
    int m0, int n0,
    const float* __restrict__ arp1, const float* __restrict__ arp2,
    const uint32_t* __restrict__ Btw,
    const float* __restrict__ bias, float* __restrict__ C, int N, int relu) {
    extern __shared__ uint32_t sm[];
    const int tid = threadIdx.x;
    const int lane = tid & 31, wid = tid >> 5;
    const int gid = lane >> 2, tig = lane & 3;
    const int wm = wid >> 1, wn = wid & 1;
    const int row = tid >> 1, ah = tid & 1;

    const char* brp = (const char*)Btw + (size_t)(n0 + row) * 1024 + ah * 16;

    uint32_t su = smem_u32(sm);
    uint32_t bdst[4];
#pragma unroll
    for (int q = 0; q < 4; q++)
        bdst[q] = su + (uint32_t)(2048 + q * 1024 + row * 8 + ah * 4) * 4;

    float acc[2][8][4];
#pragma unroll
    for (int mi = 0; mi < 2; mi++)
#pragma unroll
        for (int ni = 0; ni < 8; ni++)
#pragma unroll
            for (int q = 0; q < 4; q++) acc[mi][ni][q] = 0.f;

    float4 pa1[2], pa2[2];

#define LDA(s) do { int _k = (s) * 16;                                        \
    pa1[0] = *(const float4*)(arp1 + _k);                                     \
    pa1[1] = *(const float4*)(arp1 + _k + 8);                                 \
    if (PAIR) {                                                               \
        pa2[0] = *(const float4*)(arp2 + _k);                                 \
        pa2[1] = *(const float4*)(arp2 + _k + 8);                             \
    } } while (0)

#define STA(b) do {                                                           \
    float f0, f1, f2, f3, f4, f5, f6, f7;                                     \
    if (PAIR) {                                                               \
        f0 = fmaxf(pa1[0].x + pa2[0].x, 0.f);                                 \
        f1 = fmaxf(pa1[0].y + pa2[0].y, 0.f);                                 \
        f2 = fmaxf(pa1[0].z + pa2[0].z, 0.f);                                 \
        f3 = fmaxf(pa1[0].w + pa2[0].w, 0.f);                                 \
        f4 = fmaxf(pa1[1].x + pa2[1].x, 0.f);                                 \
        f5 = fmaxf(pa1[1].y + pa2[1].y, 0.f);                                 \
        f6 = fmaxf(pa1[1].z + pa2[1].z, 0.f);                                 \
        f7 = fmaxf(pa1[1].w + pa2[1].w, 0.f);                                 \
    } else {                                                                  \
        f0 = pa1[0].x; f1 = pa1[0].y; f2 = pa1[0].z; f3 = pa1[0].w;           \
        f4 = pa1[1].x; f5 = pa1[1].y; f6 = pa1[1].z; f7 = pa1[1].w;           \
    }                                                                         \
    uint4 q = make_uint4(packbf(f0, f1), packbf(f4, f5),                      \
                         packbf(f2, f3), packbf(f6, f7));                     \
    *(uint4*)&sm[(b) * 1024 + row * 8 + ah * 4] = q; } while (0)

#define LDB(s, q) do { if ((s) < 32)                                          \
        CP_ASYNC16(bdst[q], brp + (s) * 32);                                  \
    CP_COMMIT(); } while (0)

#define COMPUTE(AB, BB) do {                                                  \
    const uint32_t* A_ = sm + (AB) * 1024;                                    \
    const uint32_t* B_ = sm + 2048 + (BB) * 1024;                             \
    uint2 bfr[8];                                                             \
    _Pragma("unroll") for (int ni = 0; ni < 8; ni++) {                        \
        int nr = wn * 64 + ni * 8 + gid;                                      \
        bfr[ni] = *(const uint2*)&B_[nr * 8 + tig * 2];                       \
    }                                                                         \
    _Pragma("unroll") for (int mi = 0; mi < 2; mi++) {                        \
        int r = wm * 32 + mi * 16 + gid;                                      \
        uint2 u0 = *(const uint2*)&A_[r * 8 + tig * 2];                       \
        uint2 u1 = *(const uint2*)&A_[(r + 8) * 8 + tig * 2];                 \
        _Pragma("unroll") for (int ni = 0; ni < 8; ni++)                      \
            mma_bf16(acc[mi][ni], u0.x, u1.x, u0.y, u1.y,                     \
                     bfr[ni].x, bfr[ni].y);                                   \
    } } while (0)

#define ITER(s, AB, BB) do {                                                  \
    if ((s) + 1 < 32) STA((AB) ^ 1);                                          \
    if ((s) + 2 < 32) LDA((s) + 2);                                           \
    LDB((s) + 3, ((BB) + 3) & 3);                                             \
    CP_WAIT(2);                                                               \
    COMPUTE(AB, BB);                                                          \
    __syncthreads(); } while (0)

    LDA(0); STA(0);
    LDB(0, 0); LDB(1, 1); LDB(2, 2);
    LDA(1);
    CP_WAIT(2);
    __syncthreads();

#pragma unroll 1
    for (int s0 = 0; s0 < 28; s0 += 4) {
        ITER(s0 + 0, 0, 0);
        ITER(s0 + 1, 1, 1);
        ITER(s0 + 2, 0, 2);
        ITER(s0 + 3, 1, 3);
    }
    ITER(28, 0, 0);
    ITER(29, 1, 1);
    ITER(30, 0, 2);
    ITER(31, 1, 3);

#undef LDA
#undef STA
#undef LDB
#undef COMPUTE
#undef ITER

    if (PAIR) {
        // epilogue: per-row partial score over this CTA's 128 cols
        float* sred = (float*)(sm + 6144);
#pragma unroll
        for (int mi = 0; mi < 2; mi++) {
            float p0 = 0.f, p1 = 0.f;
#pragma unroll
            for (int ni = 0; ni < 8; ni++) {
                int nn = n0 + wn * 64 + ni * 8 + 2 * tig;
                float b2a = g_b2p[nn],     w3a = g_w3p[nn];
                float b2b = g_b2p[nn + 1], w3b = g_w3p[nn + 1];
                p0 += fmaxf(acc[mi][ni][0] + b2a, 0.f) * w3a
                    + fmaxf(acc[mi][ni][1] + b2b, 0.f) * w3b;
                p1 += fmaxf(acc[mi][ni][2] + b2a, 0.f) * w3a
                    + fmaxf(acc[mi][ni][3] + b2b, 0.f) * w3b;
            }
            p0 += __shfl_xor_sync(0xFFFFFFFFu, p0, 1);
            p0 += __shfl_xor_sync(0xFFFFFFFFu, p0, 2);
            p1 += __shfl_xor_sync(0xFFFFFFFFu, p1, 1);
            p1 += __shfl_xor_sync(0xFFFFFFFFu, p1, 2);
            if (tig == 0) {
                int r = wm * 32 + mi * 16 + gid;
                sred[r * 2 + wn] = p0;
                sred[(r + 8) * 2 + wn] = p1;
            }
        }
        __syncthreads();
        if (tid < 128)
            g_scpart[blockIdx.x * NPAIR + m0 + tid] = sred[tid * 2] + sred[tid * 2 + 1];
    } else {
#pragma unroll
        for (int mi = 0; mi < 2; mi++) {
            int r = m0 + wm * 32 + mi * 16 + gid;
#pragma unroll
            for (int ni = 0; ni < 8; ni++) {
                int nn = n0 + wn * 64 + ni * 8 + 2 * tig;
                float ba = (bias && nn < N) ? bias[nn] : 0.f;
                float bb = (bias && nn + 1 < N) ? bias[nn + 1] : 0.f;
                float c0 = (nn < N) ? acc[mi][ni][0] + ba : 0.f;
                float c1 = (nn + 1 < N) ? acc[mi][ni][1] + bb : 0.f;
                float c2 = (nn < N) ? acc[mi][ni][2] + ba : 0.f;
                float c3 = (nn + 1 < N) ? acc[mi][ni][3] + bb : 0.f;
                if (relu) {
                    c0 = fmaxf(c0, 0.f); c1 = fmaxf(c1, 0.f);
                    c2 = fmaxf(c2, 0.f); c3 = fmaxf(c3, 0.f);
                }
                *(float2*)&C[(size_t)r * DMODEL + nn] = make_float2(c0, c1);
                *(float2*)&C[(size_t)(r + 8) * DMODEL + nn] = make_float2(c2, c3);
            }
        }
    }
}

// ---------------- kernel wrappers ----------------
__global__ void __launch_bounds__(256, 2) pair_mma_kernel(const int* __restrict__ s2c) {
    const int m0 = blockIdx.y * 128;
    const int row = threadIdx.x >> 1, ah = threadIdx.x & 1;
    int p = m0 + row, nsp = p / 65, l = p - nsp * 65;
    const float* a1 = g_span_part + (size_t)nsp * DMODEL + ah * 4;
    const float* a2 = ((l < LMAX)
        ? g_know_part + (size_t)s2c[nsp * LMAX + l] * DMODEL
        : g_sent_part + (size_t)nsp * DMODEL) + ah * 4;
    gemm_core_bf16<true>(m0, blockIdx.x * 128, a1, a2, g_W2b, nullptr, nullptr, 0, 0);
}

__global__ void __launch_bounds__(256, 2) small_multi_kernel(
    const float* __restrict__ span, const float* __restrict__ know,
    const float* __restrict__ bs, const float* __restrict__ b1) {
    int z = blockIdx.z;
    if (z < 2 && blockIdx.y >= 2) return;
    const float* A; const uint32_t* Bw; const float* bias; float* C; int N; int relu;
    if (z == 0)      { A = span; Bw = g_Wsb;  bias = bs;      C = g_sentinel;  N = DMODEL; relu = 1; }
    else if (z == 1) { A = span; Bw = g_W1ab; bias = b1;      C = g_span_part; N = HID;    relu = 0; }
    else             { A = know; Bw = g_W1bb; bias = nullptr; C = g_know_part; N = HID;    relu = 0; }
    const int m0 = blockIdx.y * 128;
    const int row = threadIdx.x >> 1, ah = threadIdx.x & 1;
    const float* a1 = A + (size_t)(m0 + row) * DMODEL + ah * 4;
    gemm_core_bf16<false>(m0, blockIdx.x * 128, a1, a1, Bw, bias, C, N, relu);
}

__global__ void __launch_bounds__(256, 2) small_sent_kernel() {
    const int m0 = blockIdx.y * 128;
    const int row = threadIdx.x >> 1, ah = threadIdx.x & 1;
    const float* a1 = g_sentinel + (size_t)(m0 + row) * DMODEL + ah * 4;
    gemm_core_bf16<false>(m0, blockIdx.x * 128, a1, a1, g_W1bb, nullptr, g_sent_part, HID, 0);
}

// ---------------- softmax + feature aggregation ----------------
__global__ void __launch_bounds__(128) softmax_features_kernel(
    const int* __restrict__ s2c, const int* __restrict__ lengths,
    const float* __restrict__ know, float* __restrict__ out) {
    int n = blockIdx.x;
    int t = threadIdx.x;
    __shared__ float sc[65];
    __shared__ const float* eptr[65];
    __shared__ float redmax, redinv;

    if (t < 65) {
        float s = 0.f;
#pragma unroll
        for (int q = 0; q < 4; q++) s += g_scpart[q * NPAIR + n * 65 + t];
        bool valid;
        const float* ep;
        if (t < LMAX) {
            int len = lengths[n];
            if (len < 1) len = 1;
            valid = t < len;
            ep = know + (size_t)s2c[n * LMAX + t] * DMODEL;
        } else {
            valid = true;
            ep = g_sentinel + (size_t)n * DMODEL;
        }
        sc[t] = valid ? s : -1e30f;
        eptr[t] = ep;
    }
    __syncthreads();
    if (t == 0) {
        float m = sc[0];
        for (int l = 1; l < 65; l++) m = fmaxf(m, sc[l]);
        redmax = m;
    }
    __syncthreads();
    float m = redmax;
    if (t < 65) sc[t] = expf(sc[t] - m);
    __syncthreads();
    if (t == 0) {
        float s = 0.f;
        for (int l = 0; l < 65; l++) s += sc[l];
        redinv = 1.f / s;
    }
    __syncthreads();
    if (t < 65) {
        sc[t] *= redinv;
        out[NSPAN * DMODEL + n * 65 + t] = sc[t];   // probs
    }
    __syncthreads();
    float a0 = 0.f, a1 = 0.f, a2 = 0.f, a3 = 0.f;
    for (int l = 0; l < 65; l++) {
        float pr = sc[l];
        const float* ep = eptr[l];
        a0 += pr * ep[t];
        a1 += pr * ep[t + 128];
        a2 += pr * ep[t + 256];
        a3 += pr * ep[t + 384];
    }
    out[n * DMODEL + t]       = a0;   // features
    out[n * DMODEL + t + 128] = a1;
    out[n * DMODEL + t + 256] = a2;
    out[n * DMODEL + t + 384] = a3;
}

// ---------------- launch ----------------
extern "C" void kernel_launch(void* const* d_in, const int* in_sizes, int n_in,
                              void* d_out, int out_size) {
    const float* span    = (const float*)d_in[0];
    const float* know    = (const float*)d_in[1];
    const int*   s2c     = (const int*)d_in[2];
    const int*   lengths = (const int*)d_in[3];
    const float* Ws      = (const float*)d_in[4];
    const float* bs      = (const float*)d_in[5];
    const float* W1      = (const float*)d_in[6];
    const float* b1      = (const float*)d_in[7];
    const float* W2      = (const float*)d_in[8];
    const float* b2      = (const float*)d_in[9];
    const float* W3      = (const float*)d_in[10];
    // d_in[11] = b3: softmax-invariant constant shift, intentionally unused.
    float* out = (float*)d_out;

    cudaFuncSetAttribute(small_multi_kernel,
                         cudaFuncAttributeMaxDynamicSharedMemorySize, SMEM_BYTES);
    cudaFuncSetAttribute(small_sent_kernel,
                         cudaFuncAttributeMaxDynamicSharedMemorySize, SMEM_BYTES);
    cudaFuncSetAttribute(pair_mma_kernel,
                         cudaFuncAttributeMaxDynamicSharedMemorySize, SMEM_BYTES);

    // all weights -> bf16x2 permuted words; pad b2/w3
    prep_kernel<<<dim3(512, 4), 256>>>(W2, Ws, W1, b2, W3);
    // sentinel / span_part / know_part concurrently (bf16)
    small_multi_kernel<<<dim3(4, 8, 3), 256, SMEM_BYTES>>>(span, know, bs, b1);
    // sent_part = sentinel @ W1b (bf16)
    small_sent_kernel<<<dim3(4, 2), 256, SMEM_BYTES>>>();
    // fused h1 -> h2 -> score partials (bf16 m16n8k16)
    pair_mma_kernel<<<dim3(4, 130), 256, SMEM_BYTES>>>(s2c);
    // softmax + features
    softmax_features_kernel<<<NSPAN, 128>>>(s2c, lengths, know, out);
}

// round 12
// speedup vs baseline: 1.7777x; 1.0961x over previous
#include <cuda_runtime.h>
#include <cuda_bf16.h>
#include <cstdint>

#define NSPAN  256
#define KKNOW  1024
#define DMODEL 512
#define LMAX   64
#define HID    500
#define NPAIR  (NSPAN * (LMAX + 1))   /* 16640 = 130 * 128 */

// ---------------- scratch (device globals; no allocation) ----------------
__device__ float    g_sentinel[NSPAN * DMODEL];   // fp32 (softmax needs it)
__device__ uint32_t g_span_b[NSPAN * 256];        // span_part bf16x2, PERMW
__device__ uint32_t g_know_b[KKNOW * 256];        // know_part bf16x2, PERMW
__device__ uint32_t g_sent_b[NSPAN * 256];        // sent_part bf16x2, PERMW
__device__ uint32_t g_W2b[DMODEL * 256];          // W2^T  bf16x2, PERMW
__device__ uint32_t g_Wsb[DMODEL * 256];          // Ws^T  bf16x2
__device__ uint32_t g_W1ab[DMODEL * 256];         // W1a^T bf16x2
__device__ uint32_t g_W1bb[DMODEL * 256];         // W1b^T bf16x2
__device__ float g_b2p[DMODEL];
__device__ float g_w3p[DMODEL];
__device__ float g_scpart[4 * NPAIR];             // per-N-tile score partials
__device__ int g_sentflag;                        // sentinel-done counter

__device__ __forceinline__ uint32_t packbf(float lo, float hi) {
    uint32_t r;
    asm("cvt.rn.bf16x2.f32 %0, %1, %2;" : "=r"(r) : "f"(hi), "f"(lo));
    return r;
}
__device__ __forceinline__ uint32_t addrelu_bf2(uint32_t a, uint32_t b) {
    __nv_bfloat162 x = __hadd2(*(__nv_bfloat162*)&a, *(__nv_bfloat162*)&b);
    __nv_bfloat162 z = __float2bfloat162_rn(0.f);
    x = __hmax2(x, z);
    return *(uint32_t*)&x;
}
__device__ __forceinline__ uint32_t smem_u32(const void* p) {
    uint32_t a;
    asm("{ .reg .u64 t; cvta.to.shared.u64 t, %1; cvt.u32.u64 %0, t; }"
        : "=r"(a) : "l"(p));
    return a;
}
__device__ __forceinline__ void mma_bf16(float* c,
                                         uint32_t a0, uint32_t a1, uint32_t a2, uint32_t a3,
                                         uint32_t b0, uint32_t b1) {
    asm volatile(
        "mma.sync.aligned.m16n8k16.row.col.f32.bf16.bf16.f32 "
        "{%0,%1,%2,%3}, {%4,%5,%6,%7}, {%8,%9}, {%0,%1,%2,%3};"
        : "+f"(c[0]), "+f"(c[1]), "+f"(c[2]), "+f"(c[3])
        : "r"(a0), "r"(a1), "r"(a2), "r"(a3), "r"(b0), "r"(b1));
}
#define CP_ASYNC16(dst, src) \
    asm volatile("cp.async.cg.shared.global [%0], [%1], 16;" \
                 :: "r"(dst), "l"(src) : "memory")
#define CP_COMMIT() asm volatile("cp.async.commit_group;" ::: "memory")
#define CP_WAIT(n)  asm volatile("cp.async.wait_group %0;" :: "n"(n) : "memory")

// word-pair permutation: pair g (cols 2g,2g+1) stored at (g&~7)+PERMW(g&7)
#define PERMW(w) ((((w) & 3) << 1) | (((w) >> 2) & 1))

// smem layout (words): A 2x1024 @0, B 4x1024 @2048, sred 256 @6144
#define SMEM_BYTES ((6144 + 256) * 4)

// ---------------- prep: weights -> bf16x2 permuted; pad b2/w3; reset flag --
__global__ void prep_kernel(const float* __restrict__ W2,
                            const float* __restrict__ Ws,
                            const float* __restrict__ W1,
                            const float* __restrict__ b2,
                            const float* __restrict__ W3) {
    int i = blockIdx.x * blockDim.x + threadIdx.x;   // 0 .. 512*256-1 (words)
    int z = blockIdx.y;
    int n = i >> 8, g = i & 255;
    int k = g * 2;
    float v0, v1;
    uint32_t* dst;
    if (z == 0) {
        v0 = (k < HID && n < HID) ? W2[k * HID + n] : 0.f;
        v1 = (k + 1 < HID && n < HID) ? W2[(k + 1) * HID + n] : 0.f;
        dst = g_W2b;
        if (i == 0) g_sentflag = 0;
        if (i < DMODEL) {
            g_b2p[i] = (i < HID) ? b2[i] : 0.f;
            g_w3p[i] = (i < HID) ? W3[i] : 0.f;
        }
    } else if (z == 1) {
        v0 = Ws[k * DMODEL + n];
        v1 = Ws[(k + 1) * DMODEL + n];
        dst = g_Wsb;
    } else if (z == 2) {
        v0 = (n < HID) ? W1[k * HID + n] : 0.f;
        v1 = (n < HID) ? W1[(k + 1) * HID + n] : 0.f;
        dst = g_W1ab;
    } else {
        v0 = (n < HID) ? W1[(k + DMODEL) * HID + n] : 0.f;
        v1 = (n < HID) ? W1[(k + 1 + DMODEL) * HID + n] : 0.f;
        dst = g_W1bb;
    }
    dst[n * 256 + (g & ~7) + PERMW(g & 7)] = packbf(v0, v1);
}

// ================= unified bf16 pipelined GEMM core =================
// CTA 128(M) x 128(N), K=512 in 32 chunks of 16. 8 warps (4M x 2N), 32x64.
// MODE 0: fp32 A -> fp32 C (+bias/relu)           [sentinel]
// MODE 1: fp32 A -> bf16x2 permuted C (+bias)     [parts]
// MODE 2: bf16 A pair (add+relu) -> score partials [pair]
template<int MODE>
__device__ __forceinline__ void gemm_core(
    int m0, int n0,
    const float* __restrict__ arpF,
    const uint4* __restrict__ arpA, const uint4* __restrict__ arpB,
    const uint32_t* __restrict__ Btw,
    const float* __restrict__ bias, void* Cout, int N, int relu) {
    extern __shared__ uint32_t sm[];
    const int tid = threadIdx.x;
    const int lane = tid & 31, wid = tid >> 5;
    const int gid = lane >> 2, tig = lane & 3;
    const int wm = wid >> 1, wn = wid & 1;
    const int row = tid >> 1, ah = tid & 1;

    const char* brp = (const char*)Btw + (size_t)(n0 + row) * 1024 + ah * 16;

    uint32_t su = smem_u32(sm);
    uint32_t bdst[4];
#pragma unroll
    for (int q = 0; q < 4; q++)
        bdst[q] = su + (uint32_t)(2048 + q * 1024 + row * 8 + ah * 4) * 4;

    float acc[2][8][4];
#pragma unroll
    for (int mi = 0; mi < 2; mi++)
#pragma unroll
        for (int ni = 0; ni < 8; ni++)
#pragma unroll
            for (int q = 0; q < 4; q++) acc[mi][ni][q] = 0.f;

    float4 pa1[2];
    uint4 ua1, ua2;

#define LDA(s) do {                                                           \
    if (MODE == 2) {                                                          \
        ua1 = arpA[(s) * 2 + ah];                                             \
        ua2 = arpB[(s) * 2 + ah];                                             \
    } else {                                                                  \
        int _k = (s) * 16;                                                    \
        pa1[0] = *(const float4*)(arpF + _k);                                 \
        pa1[1] = *(const float4*)(arpF + _k + 8);                             \
    } } while (0)

#define STA(b) do {                                                           \
    uint4 q;                                                                  \
    if (MODE == 2) {                                                          \
        q.x = addrelu_bf2(ua1.x, ua2.x);                                      \
        q.y = addrelu_bf2(ua1.y, ua2.y);                                      \
        q.z = addrelu_bf2(ua1.z, ua2.z);                                      \
        q.w = addrelu_bf2(ua1.w, ua2.w);                                      \
    } else {                                                                  \
        q = make_uint4(packbf(pa1[0].x, pa1[0].y), packbf(pa1[1].x, pa1[1].y),\
                       packbf(pa1[0].z, pa1[0].w), packbf(pa1[1].z, pa1[1].w));\
    }                                                                         \
    *(uint4*)&sm[(b) * 1024 + row * 8 + ah * 4] = q; } while (0)

#define LDB(s, q) do { if ((s) < 32)                                          \
        CP_ASYNC16(bdst[q], brp + (s) * 32);                                  \
    CP_COMMIT(); } while (0)

#define COMPUTE(AB, BB) do {                                                  \
    const uint32_t* A_ = sm + (AB) * 1024;                                    \
    const uint32_t* B_ = sm + 2048 + (BB) * 1024;                             \
    uint2 bfr[8];                                                             \
    _Pragma("unroll") for (int ni = 0; ni < 8; ni++) {                        \
        int nr = wn * 64 + ni * 8 + gid;                                      \
        bfr[ni] = *(const uint2*)&B_[nr * 8 + tig * 2];                       \
    }                                                                         \
    _Pragma("unroll") for (int mi = 0; mi < 2; mi++) {                        \
        int r = wm * 32 + mi * 16 + gid;                                      \
        uint2 u0 = *(const uint2*)&A_[r * 8 + tig * 2];                       \
        uint2 u1 = *(const uint2*)&A_[(r + 8) * 8 + tig * 2];                 \
        _Pragma("unroll") for (int ni = 0; ni < 8; ni++)                      \
            mma_bf16(acc[mi][ni], u0.x, u1.x, u0.y, u1.y,                     \
                     bfr[ni].x, bfr[ni].y);                                   \
    } } while (0)

#define ITER(s, AB, BB) do {                                                  \
    if ((s) + 1 < 32) STA((AB) ^ 1);                                          \
    if ((s) + 2 < 32) LDA((s) + 2);                                           \
    LDB((s) + 3, ((BB) + 3) & 3);                                             \
    CP_WAIT(2);                                                               \
    COMPUTE(AB, BB);                                                          \
    __syncthreads(); } while (0)

    LDA(0); STA(0);
    LDB(0, 0); LDB(1, 1); LDB(2, 2);
    LDA(1);
    CP_WAIT(2);
    __syncthreads();

#pragma unroll 1
    for (int s0 = 0; s0 < 28; s0 += 4) {
        ITER(s0 + 0, 0, 0);
        ITER(s0 + 1, 1, 1);
        ITER(s0 + 2, 0, 2);
        ITER(s0 + 3, 1, 3);
    }
    ITER(28, 0, 0);
    ITER(29, 1, 1);
    ITER(30, 0, 2);
    ITER(31, 1, 3);

#undef LDA
#undef STA
#undef LDB
#undef COMPUTE
#undef ITER

    if (MODE == 2) {
        // epilogue: per-row partial score over this CTA's 128 cols
        float* sred = (float*)(sm + 6144);
#pragma unroll
        for (int mi = 0; mi < 2; mi++) {
            float p0 = 0.f, p1 = 0.f;
#pragma unroll
            for (int ni = 0; ni < 8; ni++) {
                int nn = n0 + wn * 64 + ni * 8 + 2 * tig;
                float b2a = g_b2p[nn],     w3a = g_w3p[nn];
                float b2b = g_b2p[nn + 1], w3b = g_w3p[nn + 1];
                p0 += fmaxf(acc[mi][ni][0] + b2a, 0.f) * w3a
                    + fmaxf(acc[mi][ni][1] + b2b, 0.f) * w3b;
                p1 += fmaxf(acc[mi][ni][2] + b2a, 0.f) * w3a
                    + fmaxf(acc[mi][ni][3] + b2b, 0.f) * w3b;
            }
            p0 += __shfl_xor_sync(0xFFFFFFFFu, p0, 1);
            p0 += __shfl_xor_sync(0xFFFFFFFFu, p0, 2);
            p1 += __shfl_xor_sync(0xFFFFFFFFu, p1, 1);
            p1 += __shfl_xor_sync(0xFFFFFFFFu, p1, 2);
            if (tig == 0) {
                int r = wm * 32 + mi * 16 + gid;
                sred[r * 2 + wn] = p0;
                sred[(r + 8) * 2 + wn] = p1;
            }
        }
        __syncthreads();
        if (tid < 128)
            g_scpart[blockIdx.x * NPAIR + m0 + tid] = sred[tid * 2] + sred[tid * 2 + 1];
    } else if (MODE == 1) {
        uint32_t* Cw = (uint32_t*)Cout;
#pragma unroll
        for (int mi = 0; mi < 2; mi++) {
            int r = m0 + wm * 32 + mi * 16 + gid;
#pragma unroll
            for (int ni = 0; ni < 8; ni++) {
                int nn = n0 + wn * 64 + ni * 8 + 2 * tig;
                float ba = (bias && nn < N) ? bias[nn] : 0.f;
                float bb = (bias && nn + 1 < N) ? bias[nn + 1] : 0.f;
                float c0 = (nn < N) ? acc[mi][ni][0] + ba : 0.f;
                float c1 = (nn + 1 < N) ? acc[mi][ni][1] + bb : 0.f;
                float c2 = (nn < N) ? acc[mi][ni][2] + ba : 0.f;
                float c3 = (nn + 1 < N) ? acc[mi][ni][3] + bb : 0.f;
                int g = nn >> 1;
                int pos = (g & ~7) + PERMW(g & 7);
                Cw[(size_t)r * 256 + pos] = packbf(c0, c1);
                Cw[(size_t)(r + 8) * 256 + pos] = packbf(c2, c3);
            }
        }
    } else {
        float* C = (float*)Cout;
#pragma unroll
        for (int mi = 0; mi < 2; mi++) {
            int r = m0 + wm * 32 + mi * 16 + gid;
#pragma unroll
            for (int ni = 0; ni < 8; ni++) {
                int nn = n0 + wn * 64 + ni * 8 + 2 * tig;
                float ba = (bias && nn < N) ? bias[nn] : 0.f;
                float bb = (bias && nn + 1 < N) ? bias[nn + 1] : 0.f;
                float c0 = (nn < N) ? acc[mi][ni][0] + ba : 0.f;
                float c1 = (nn + 1 < N) ? acc[mi][ni][1] + bb : 0.f;
                float c2 = (nn < N) ? acc[mi][ni][2] + ba : 0.f;
                float c3 = (nn + 1 < N) ? acc[mi][ni][3] + bb : 0.f;
                if (relu) {
                    c0 = fmaxf(c0, 0.f); c1 = fmaxf(c1, 0.f);
                    c2 = fmaxf(c2, 0.f); c3 = fmaxf(c3, 0.f);
                }
                *(float2*)&C[(size_t)r * DMODEL + nn] = make_float2(c0, c1);
                *(float2*)&C[(size_t)(r + 8) * DMODEL + nn] = make_float2(c2, c3);
            }
        }
    }
}

// ---------------- kernel wrappers ----------------
__global__ void __launch_bounds__(256, 2) pair_mma_kernel(const int* __restrict__ s2c) {
    const int m0 = blockIdx.y * 128;
    const int row = threadIdx.x >> 1;
    int p = m0 + row, nsp = p / 65, l = p - nsp * 65;
    const uint4* a1 = (const uint4*)(g_span_b + (size_t)nsp * 256);
    const uint4* a2 = (l < LMAX)
        ? (const uint4*)(g_know_b + (size_t)s2c[nsp * LMAX + l] * 256)
        : (const uint4*)(g_sent_b + (size_t)nsp * 256);
    gemm_core<2>(m0, blockIdx.x * 128, nullptr, a1, a2, g_W2b,
                 nullptr, nullptr, 0, 0);
}

// sentinel(z0) / span_part(z1) / know_part(z2) / sent_part(z3, waits on z0)
__global__ void __launch_bounds__(256, 2) small_multi_kernel(
    const float* __restrict__ span, const float* __restrict__ know,
    const float* __restrict__ bs, const float* __restrict__ b1) {
    int z = blockIdx.z;
    if (z != 2 && blockIdx.y >= 2) return;
    const int m0 = blockIdx.y * 128;
    const int n0 = blockIdx.x * 128;
    const int row = threadIdx.x >> 1, ah = threadIdx.x & 1;
    if (z == 0) {
        const float* a = span + (size_t)(m0 + row) * DMODEL + ah * 4;
        gemm_core<0>(m0, n0, a, nullptr, nullptr, g_Wsb, bs, g_sentinel, DMODEL, 1);
        __syncthreads();
        if (threadIdx.x == 0) { __threadfence(); atomicAdd(&g_sentflag, 1); }
    } else if (z == 1) {
        const float* a = span + (size_t)(m0 + row) * DMODEL + ah * 4;
        gemm_core<1>(m0, n0, a, nullptr, nullptr, g_W1ab, b1, g_span_b, HID, 0);
    } else if (z == 2) {
        const float* a = know + (size_t)(m0 + row) * DMODEL + ah * 4;
        gemm_core<1>(m0, n0, a, nullptr, nullptr, g_W1bb, nullptr, g_know_b, HID, 0);
    } else {
        if (threadIdx.x == 0) {
            while (atomicAdd(&g_sentflag, 0) < 8) __nanosleep(64);
        }
        __syncthreads();
        const float* a = g_sentinel + (size_t)(m0 + row) * DMODEL + ah * 4;
        gemm_core<1>(m0, n0, a, nullptr, nullptr, g_W1bb, nullptr, g_sent_b, HID, 0);
    }
}

// ---------------- softmax + feature aggregation ----------------
__global__ void __launch_bounds__(128) softmax_features_kernel(
    const int* __restrict__ s2c, const int* __restrict__ lengths,
    const float* __restrict__ know, float* __restrict__ out) {
    int n = blockIdx.x;
    int t = threadIdx.x;
    __shared__ float sc[65];
    __shared__ const float* eptr[65];
    __shared__ float redmax, redinv;

    if (t < 65) {
        float s = 0.f;
#pragma unroll
        for (int q = 0; q < 4; q++) s += g_scpart[q * NPAIR + n * 65 + t];
        bool valid;
        const float* ep;
        if (t < LMAX) {
            int len = lengths[n];
            if (len < 1) len = 1;
            valid = t < len;
            ep = know + (size_t)s2c[n * LMAX + t] * DMODEL;
        } else {
            valid = true;
            ep = g_sentinel + (size_t)n * DMODEL;
        }
        sc[t] = valid ? s : -1e30f;
        eptr[t] = ep;
    }
    __syncthreads();
    if (t == 0) {
        float m = sc[0];
        for (int l = 1; l < 65; l++) m = fmaxf(m, sc[l]);
        redmax = m;
    }
    __syncthreads();
    float m = redmax;
    if (t < 65) sc[t] = expf(sc[t] - m);
    __syncthreads();
    if (t == 0) {
        float s = 0.f;
        for (int l = 0; l < 65; l++) s += sc[l];
        redinv = 1.f / s;
    }
    __syncthreads();
    if (t < 65) {
        sc[t] *= redinv;
        out[NSPAN * DMODEL + n * 65 + t] = sc[t];   // probs
    }
    __syncthreads();
    float a0 = 0.f, a1 = 0.f, a2 = 0.f, a3 = 0.f;
    for (int l = 0; l < 65; l++) {
        float pr = sc[l];
        const float* ep = eptr[l];
        a0 += pr * ep[t];
        a1 += pr * ep[t + 128];
        a2 += pr * ep[t + 256];
        a3 += pr * ep[t + 384];
    }
    out[n * DMODEL + t]       = a0;   // features
    out[n * DMODEL + t + 128] = a1;
    out[n * DMODEL + t + 256] = a2;
    out[n * DMODEL + t + 384] = a3;
}

// ---------------- launch ----------------
extern "C" void kernel_launch(void* const* d_in, const int* in_sizes, int n_in,
                              void* d_out, int out_size) {
    const float* span    = (const float*)d_in[0];
    const float* know    = (const float*)d_in[1];
    const int*   s2c     = (const int*)d_in[2];
    const int*   lengths = (const int*)d_in[3];
    const float* Ws      = (const float*)d_in[4];
    const float* bs      = (const float*)d_in[5];
    const float* W1      = (const float*)d_in[6];
    const float* b1      = (const float*)d_in[7];
    const float* W2      = (const float*)d_in[8];
    const float* b2      = (const float*)d_in[9];
    const float* W3      = (const float*)d_in[10];
    // d_in[11] = b3: softmax-invariant constant shift, intentionally unused.
    float* out = (float*)d_out;

    cudaFuncSetAttribute(small_multi_kernel,
                         cudaFuncAttributeMaxDynamicSharedMemorySize, SMEM_BYTES);
    cudaFuncSetAttribute(pair_mma_kernel,
                         cudaFuncAttributeMaxDynamicSharedMemorySize, SMEM_BYTES);

    // weights -> bf16x2 permuted; pad b2/w3; reset sent flag
    prep_kernel<<<dim3(512, 4), 256>>>(W2, Ws, W1, b2, W3);
    // sentinel / span_part / know_part / sent_part in ONE launch
    small_multi_kernel<<<dim3(4, 8, 4), 256, SMEM_BYTES>>>(span, know, bs, b1);
    // fused h1 -> h2 -> score partials (bf16 A gathered as packed parts)
    pair_mma_kernel<<<dim3(4, 130), 256, SMEM_BYTES>>>(s2c);
    // softmax + features
    softmax_features_kernel<<<NSPAN, 128>>>(s2c, lengths, know, out);
}

// round 13
// speedup vs baseline: 1.8097x; 1.0180x over previous
#include <cuda_runtime.h>
#include <cuda_bf16.h>
#include <cstdint>

#define NSPAN  256
#define KKNOW  1024
#define DMODEL 512
#define LMAX   64
#define HID    500
#define NPAIR  (NSPAN * (LMAX + 1))   /* 16640 = 130 * 128 */

// ---------------- scratch (device globals; no allocation) ----------------
__device__ float    g_sentinel[NSPAN * DMODEL];   // fp32 (softmax needs it)
__device__ uint32_t g_span_b[NSPAN * 256];        // span_part bf16x2, PERMW
__device__ uint32_t g_know_b[KKNOW * 256];        // know_part bf16x2, PERMW
__device__ uint32_t g_sent_b[NSPAN * 256];        // sent_part bf16x2, PERMW
__device__ uint32_t g_W2b[DMODEL * 256];          // W2^T  bf16x2, PERMW
__device__ uint32_t g_Wsb[DMODEL * 256];          // Ws^T  bf16x2
__device__ uint32_t g_W1ab[DMODEL * 256];         // W1a^T bf16x2
__device__ uint32_t g_W1bb[DMODEL * 256];         // W1b^T bf16x2
__device__ float g_b2p[DMODEL];
__device__ float g_w3p[DMODEL];
__device__ float g_scpart[4 * NPAIR];             // per-N-tile score partials
__device__ int g_sentflag;                        // sentinel-done counter

__device__ __forceinline__ uint32_t packbf(float lo, float hi) {
    uint32_t r;
    asm("cvt.rn.bf16x2.f32 %0, %1, %2;" : "=r"(r) : "f"(hi), "f"(lo));
    return r;
}
__device__ __forceinline__ uint32_t addrelu_bf2(uint32_t a, uint32_t b) {
    __nv_bfloat162 x = __hadd2(*(__nv_bfloat162*)&a, *(__nv_bfloat162*)&b);
    __nv_bfloat162 z = __float2bfloat162_rn(0.f);
    x = __hmax2(x, z);
    return *(uint32_t*)&x;
}
__device__ __forceinline__ uint32_t smem_u32(const void* p) {
    uint32_t a;
    asm("{ .reg .u64 t; cvta.to.shared.u64 t, %1; cvt.u32.u64 %0, t; }"
        : "=r"(a) : "l"(p));
    return a;
}
__device__ __forceinline__ void mma_bf16(float* c,
                                         uint32_t a0, uint32_t a1, uint32_t a2, uint32_t a3,
                                         uint32_t b0, uint32_t b1) {
    asm volatile(
        "mma.sync.aligned.m16n8k16.row.col.f32.bf16.bf16.f32 "
        "{%0,%1,%2,%3}, {%4,%5,%6,%7}, {%8,%9}, {%0,%1,%2,%3};"
        : "+f"(c[0]), "+f"(c[1]), "+f"(c[2]), "+f"(c[3])
        : "r"(a0), "r"(a1), "r"(a2), "r"(a3), "r"(b0), "r"(b1));
}
#define CP_ASYNC16(dst, src) \
    asm volatile("cp.async.cg.shared.global [%0], [%1], 16;" \
                 :: "r"(dst), "l"(src) : "memory")
#define CP_COMMIT() asm volatile("cp.async.commit_group;" ::: "memory")
#define CP_WAIT(n)  asm volatile("cp.async.wait_group %0;" :: "n"(n) : "memory")

// word-pair permutation: pair g (cols 2g,2g+1) stored at (g&~7)+PERMW(g&7)
#define PERMW(w) ((((w) & 3) << 1) | (((w) >> 2) & 1))

// smem layout (words): A 2x1024 @0, B 4x1024 @2048, sred 256 @6144
#define SMEM_BYTES ((6144 + 256) * 4)

// ---------------- prep v2: smem tile transpose, coalesced both sides -------
// grid (64, 4): 8x8 tiles of 64(n) x 64(k) per matrix; 256 threads.
__global__ void __launch_bounds__(256) prep_kernel(
    const float* __restrict__ W2, const float* __restrict__ Ws,
    const float* __restrict__ W1, const float* __restrict__ b2,
    const float* __restrict__ W3) {
    __shared__ float ts[64][65];
    const int z = blockIdx.y;
    const int tile = blockIdx.x;
    const int tn = (tile & 7) * 64;
    const int tk = (tile >> 3) * 64;
    const int tid = threadIdx.x;

    if (z == 0 && tile == 0 && tid == 0) g_sentflag = 0;
    if (z == 0 && tile < 2) {
        int i = tile * 256 + tid;
        g_b2p[i] = (i < HID) ? b2[i] : 0.f;
        g_w3p[i] = (i < HID) ? W3[i] : 0.f;
    }

    // coalesced read: consecutive threads -> consecutive n
    const int nl = tid & 63;
    const int kb = tid >> 6;                 // 0..3
    const int n = tn + nl;
#pragma unroll
    for (int i = 0; i < 16; i++) {
        int kl = kb * 16 + i;
        int k = tk + kl;
        float v;
        if (z == 0)      v = (k < HID && n < HID) ? W2[k * HID + n] : 0.f;
        else if (z == 1) v = Ws[k * DMODEL + n];
        else if (z == 2) v = (n < HID) ? W1[k * HID + n] : 0.f;
        else             v = (n < HID) ? W1[(k + DMODEL) * HID + n] : 0.f;
        ts[kl][nl] = v;
    }
    __syncthreads();

    uint32_t* dst = (z == 0) ? g_W2b : (z == 1) ? g_Wsb : (z == 2) ? g_W1ab : g_W1bb;
    const int wn = tid >> 2;                 // local n (0..63)
    const int gblk = tid & 3;                // 8-word group (0..3)
    uint32_t wbuf[8];
#pragma unroll
    for (int j = 0; j < 8; j++) {
        int kk = (gblk * 8 + j) * 2;         // local k pair base
        wbuf[PERMW(j)] = packbf(ts[kk][wn], ts[kk + 1][wn]);
    }
    uint32_t* o = dst + (size_t)(tn + wn) * 256 + tk / 2 + gblk * 8;
    *(uint4*)&o[0] = *(uint4*)&wbuf[0];
    *(uint4*)&o[4] = *(uint4*)&wbuf[4];
}

// ================= unified bf16 pipelined GEMM core =================
// CTA 128(M) x 128(N), K=512 in 32 chunks of 16. 8 warps (4M x 2N), 32x64.
// MODE 0: fp32 A -> fp32 C (+bias/relu)           [sentinel]
// MODE 1: fp32 A -> bf16x2 permuted C (+bias)     [parts]
// MODE 2: bf16 A pair (add+relu) -> score partials [pair]
template<int MODE>
__device__ __forceinline__ void gemm_core(
    int m0, int n0,
    const float* __restrict__ arpF,
    const uint4* __restrict__ arpA, const uint4* __restrict__ arpB,
    const uint32_t* __restrict__ Btw,
    const float* __restrict__ bias, void* Cout, int N, int relu) {
    extern __shared__ uint32_t sm[];
    const int tid = threadIdx.x;
    const int lane = tid & 31, wid = tid >> 5;
    const int gid = lane >> 2, tig = lane & 3;
    const int wm = wid >> 1, wn = wid & 1;
    const int row = tid >> 1, ah = tid & 1;

    const char* brp = (const char*)Btw + (size_t)(n0 + row) * 1024 + ah * 16;

    uint32_t su = smem_u32(sm);
    uint32_t bdst[4];
#pragma unroll
    for (int q = 0; q < 4; q++)
        bdst[q] = su + (uint32_t)(2048 + q * 1024 + row * 8 + ah * 4) * 4;

    float acc[2][8][4];
#pragma unroll
    for (int mi = 0; mi < 2; mi++)
#pragma unroll
        for (int ni = 0; ni < 8; ni++)
#pragma unroll
            for (int q = 0; q < 4; q++) acc[mi][ni][q] = 0.f;

    float4 pa1[2];
    uint4 ua1, ua2;

#define LDA(s) do {                                                           \
    if (MODE == 2) {                                                          \
        ua1 = arpA[(s) * 2 + ah];                                             \
        ua2 = arpB[(s) * 2 + ah];                                             \
    } else {                                                                  \
        int _k = (s) * 16;                                                    \
        pa1[0] = *(const float4*)(arpF + _k);                                 \
        pa1[1] = *(const float4*)(arpF + _k + 8);                             \
    } } while (0)

#define STA(b) do {                                                           \
    uint4 q;                                                                  \
    if (MODE == 2) {                                                          \
        q.x = addrelu_bf2(ua1.x, ua2.x);                                      \
        q.y = addrelu_bf2(ua1.y, ua2.y);                                      \
        q.z = addrelu_bf2(ua1.z, ua2.z);                                      \
        q.w = addrelu_bf2(ua1.w, ua2.w);                                      \
    } else {                                                                  \
        q = make_uint4(packbf(pa1[0].x, pa1[0].y), packbf(pa1[1].x, pa1[1].y),\
                       packbf(pa1[0].z, pa1[0].w), packbf(pa1[1].z, pa1[1].w));\
    }                                                                         \
    *(uint4*)&sm[(b) * 1024 + row * 8 + ah * 4] = q; } while (0)

#define LDB(s, q) do { if ((s) < 32)                                          \
        CP_ASYNC16(bdst[q], brp + (s) * 32);                                  \
    CP_COMMIT(); } while (0)

#define COMPUTE(AB, BB) do {                                                  \
    const uint32_t* A_ = sm + (AB) * 1024;                                    \
    const uint32_t* B_ = sm + 2048 + (BB) * 1024;                             \
    uint2 bfr[8];                                                             \
    _Pragma("unroll") for (int ni = 0; ni < 8; ni++) {                        \
        int nr = wn * 64 + ni * 8 + gid;                                      \
        bfr[ni] = *(const uint2*)&B_[nr * 8 + tig * 2];                       \
    }                                                                         \
    _Pragma("unroll") for (int mi = 0; mi < 2; mi++) {                        \
        int r = wm * 32 + mi * 16 + gid;                                      \
        uint2 u0 = *(const uint2*)&A_[r * 8 + tig * 2];                       \
        uint2 u1 = *(const uint2*)&A_[(r + 8) * 8 + tig * 2];                 \
        _Pragma("unroll") for (int ni = 0; ni < 8; ni++)                      \
            mma_bf16(acc[mi][ni], u0.x, u1.x, u0.y, u1.y,                     \
                     bfr[ni].x, bfr[ni].y);                                   \
    } } while (0)

#define ITER(s, AB, BB) do {                                                  \
    if ((s) + 1 < 32) STA((AB) ^ 1);                                          \
    if ((s) + 2 < 32) LDA((s) + 2);                                           \
    LDB((s) + 3, ((BB) + 3) & 3);                                             \
    CP_WAIT(2);                                                               \
    COMPUTE(AB, BB);                                                          \
    __syncthreads(); } while (0)

    LDA(0); STA(0);
    LDB(0, 0); LDB(1, 1); LDB(2, 2);
    LDA(1);
    CP_WAIT(2);
    __syncthreads();

#pragma unroll 1
    for (int s0 = 0; s0 < 28; s0 += 4) {
        ITER(s0 + 0, 0, 0);
        ITER(s0 + 1, 1, 1);
        ITER(s0 + 2, 0, 2);
        ITER(s0 + 3, 1, 3);
    }
    ITER(28, 0, 0);
    ITER(29, 1, 1);
    ITER(30, 0, 2);
    ITER(31, 1, 3);

#undef LDA
#undef STA
#undef LDB
#undef COMPUTE
#undef ITER

    if (MODE == 2) {
        // epilogue: per-row partial score over this CTA's 128 cols
        float* sred = (float*)(sm + 6144);
#pragma unroll
        for (int mi = 0; mi < 2; mi++) {
            float p0 = 0.f, p1 = 0.f;
#pragma unroll
            for (int ni = 0; ni < 8; ni++) {
                int nn = n0 + wn * 64 + ni * 8 + 2 * tig;
                float b2a = g_b2p[nn],     w3a = g_w3p[nn];
                float b2b = g_b2p[nn + 1], w3b = g_w3p[nn + 1];
                p0 += fmaxf(acc[mi][ni][0] + b2a, 0.f) * w3a
                    + fmaxf(acc[mi][ni][1] + b2b, 0.f) * w3b;
                p1 += fmaxf(acc[mi][ni][2] + b2a, 0.f) * w3a
                    + fmaxf(acc[mi][ni][3] + b2b, 0.f) * w3b;
            }
            p0 += __shfl_xor_sync(0xFFFFFFFFu, p0, 1);
            p0 += __shfl_xor_sync(0xFFFFFFFFu, p0, 2);
            p1 += __shfl_xor_sync(0xFFFFFFFFu, p1, 1);
            p1 += __shfl_xor_sync(0xFFFFFFFFu, p1, 2);
            if (tig == 0) {
                int r = wm * 32 + mi * 16 + gid;
                sred[r * 2 + wn] = p0;
                sred[(r + 8) * 2 + wn] = p1;
            }
        }
        __syncthreads();
        if (tid < 128)
            g_scpart[blockIdx.x * NPAIR + m0 + tid] = sred[tid * 2] + sred[tid * 2 + 1];
    } else if (MODE == 1) {
        uint32_t* Cw = (uint32_t*)Cout;
#pragma unroll
        for (int mi = 0; mi < 2; mi++) {
            int r = m0 + wm * 32 + mi * 16 + gid;
#pragma unroll
            for (int ni = 0; ni < 8; ni++) {
                int nn = n0 + wn * 64 + ni * 8 + 2 * tig;
                float ba = (bias && nn < N) ? bias[nn] : 0.f;
                float bb = (bias && nn + 1 < N) ? bias[nn + 1] : 0.f;
                float c0 = (nn < N) ? acc[mi][ni][0] + ba : 0.f;
                float c1 = (nn + 1 < N) ? acc[mi][ni][1] + bb : 0.f;
                float c2 = (nn < N) ? acc[mi][ni][2] + ba : 0.f;
                float c3 = (nn + 1 < N) ? acc[mi][ni][3] + bb : 0.f;
                int g = nn >> 1;
                int pos = (g & ~7) + PERMW(g & 7);
                Cw[(size_t)r * 256 + pos] = packbf(c0, c1);
                Cw[(size_t)(r + 8) * 256 + pos] = packbf(c2, c3);
            }
        }
    } else {
        float* C = (float*)Cout;
#pragma unroll
        for (int mi = 0; mi < 2; mi++) {
            int r = m0 + wm * 32 + mi * 16 + gid;
#pragma unroll
            for (int ni = 0; ni < 8; ni++) {
                int nn = n0 + wn * 64 + ni * 8 + 2 * tig;
                float ba = (bias && nn < N) ? bias[nn] : 0.f;
                float bb = (bias && nn + 1 < N) ? bias[nn + 1] : 0.f;
                float c0 = (nn < N) ? acc[mi][ni][0] + ba : 0.f;
                float c1 = (nn + 1 < N) ? acc[mi][ni][1] + bb : 0.f;
                float c2 = (nn < N) ? acc[mi][ni][2] + ba : 0.f;
                float c3 = (nn + 1 < N) ? acc[mi][ni][3] + bb : 0.f;
                if (relu) {
                    c0 = fmaxf(c0, 0.f); c1 = fmaxf(c1, 0.f);
                    c2 = fmaxf(c2, 0.f); c3 = fmaxf(c3, 0.f);
                }
                *(float2*)&C[(size_t)r * DMODEL + nn] = make_float2(c0, c1);
                *(float2*)&C[(size_t)(r + 8) * DMODEL + nn] = make_float2(c2, c3);
            }
        }
    }
}

// ---------------- kernel wrappers ----------------
__global__ void __launch_bounds__(256, 2) pair_mma_kernel(const int* __restrict__ s2c) {
    const int m0 = blockIdx.y * 128;
    const int row = threadIdx.x >> 1;
    int p = m0 + row, nsp = p / 65, l = p - nsp * 65;
    const uint4* a1 = (const uint4*)(g_span_b + (size_t)nsp * 256);
    const uint4* a2 = (l < LMAX)
        ? (const uint4*)(g_know_b + (size_t)s2c[nsp * LMAX + l] * 256)
        : (const uint4*)(g_sent_b + (size_t)nsp * 256);
    gemm_core<2>(m0, blockIdx.x * 128, nullptr, a1, a2, g_W2b,
                 nullptr, nullptr, 0, 0);
}

// sentinel(z0) / span_part(z1) / know_part(z2) / sent_part(z3, waits on z0)
__global__ void __launch_bounds__(256, 2) small_multi_kernel(
    const float* __restrict__ span, const float* __restrict__ know,
    const float* __restrict__ bs, const float* __restrict__ b1) {
    int z = blockIdx.z;
    if (z != 2 && blockIdx.y >= 2) return;
    const int m0 = blockIdx.y * 128;
    const int n0 = blockIdx.x * 128;
    const int row = threadIdx.x >> 1, ah = threadIdx.x & 1;
    if (z == 0) {
        const float* a = span + (size_t)(m0 + row) * DMODEL + ah * 4;
        gemm_core<0>(m0, n0, a, nullptr, nullptr, g_Wsb, bs, g_sentinel, DMODEL, 1);
        __syncthreads();
        if (threadIdx.x == 0) { __threadfence(); atomicAdd(&g_sentflag, 1); }
    } else if (z == 1) {
        const float* a = span + (size_t)(m0 + row) * DMODEL + ah * 4;
        gemm_core<1>(m0, n0, a, nullptr, nullptr, g_W1ab, b1, g_span_b, HID, 0);
    } else if (z == 2) {
        const float* a = know + (size_t)(m0 + row) * DMODEL + ah * 4;
        gemm_core<1>(m0, n0, a, nullptr, nullptr, g_W1bb, nullptr, g_know_b, HID, 0);
    } else {
        if (threadIdx.x == 0) {
            while (atomicAdd(&g_sentflag, 0) < 8) __nanosleep(64);
        }
        __syncthreads();
        const float* a = g_sentinel + (size_t)(m0 + row) * DMODEL + ah * 4;
        gemm_core<1>(m0, n0, a, nullptr, nullptr, g_W1bb, nullptr, g_sent_b, HID, 0);
    }
}

// ---------------- softmax + feature aggregation (v2: 256 thr, shfl red) ----
__global__ void __launch_bounds__(256) softmax_features_kernel(
    const int* __restrict__ s2c, const int* __restrict__ lengths,
    const float* __restrict__ know, float* __restrict__ out) {
    int n = blockIdx.x;
    int t = threadIdx.x;
    __shared__ float sc[65];
    __shared__ const float* eptr[65];
    __shared__ float rmax, rinv;

    if (t < 65) {
        float s = 0.f;
#pragma unroll
        for (int q = 0; q < 4; q++) s += g_scpart[q * NPAIR + n * 65 + t];
        bool valid;
        const float* ep;
        if (t < LMAX) {
            int len = lengths[n];
            if (len < 1) len = 1;
            valid = t < len;
            ep = know + (size_t)s2c[n * LMAX + t] * DMODEL;
        } else {
            valid = true;
            ep = g_sentinel + (size_t)n * DMODEL;
        }
        sc[t] = valid ? s : -1e30f;
        eptr[t] = ep;
    }
    __syncthreads();
    if (t < 32) {
        float v = fmaxf(sc[t], sc[t + 32]);
        if (t == 0) v = fmaxf(v, sc[64]);
#pragma unroll
        for (int o = 16; o; o >>= 1)
            v = fmaxf(v, __shfl_xor_sync(0xFFFFFFFFu, v, o));
        if (t == 0) rmax = v;
    }
    __syncthreads();
    float m = rmax;
    if (t < 65) sc[t] = expf(sc[t] - m);
    __syncthreads();
    if (t < 32) {
        float v = sc[t] + sc[t + 32];
        if (t == 0) v += sc[64];
#pragma unroll
        for (int o = 16; o; o >>= 1)
            v += __shfl_xor_sync(0xFFFFFFFFu, v, o);
        if (t == 0) rinv = 1.f / v;
    }
    __syncthreads();
    float inv = rinv;
    if (t < 65) {
        sc[t] *= inv;
        out[NSPAN * DMODEL + n * 65 + t] = sc[t];   // probs
    }
    __syncthreads();
    // features: each thread owns 2 consecutive dims (float2, coalesced)
    float a0 = 0.f, a1 = 0.f;
#pragma unroll 5
    for (int l = 0; l < 65; l++) {
        float pr = sc[l];
        float2 e = *(const float2*)&eptr[l][2 * t];
        a0 += pr * e.x;
        a1 += pr * e.y;
    }
    *(float2*)&out[n * DMODEL + 2 * t] = make_float2(a0, a1);
}

// ---------------- launch ----------------
extern "C" void kernel_launch(void* const* d_in, const int* in_sizes, int n_in,
                              void* d_out, int out_size) {
    const float* span    = (const float*)d_in[0];
    const float* know    = (const float*)d_in[1];
    const int*   s2c     = (const int*)d_in[2];
    const int*   lengths = (const int*)d_in[3];
    const float* Ws      = (const float*)d_in[4];
    const float* bs      = (const float*)d_in[5];
    const float* W1      = (const float*)d_in[6];
    const float* b1      = (const float*)d_in[7];
    const float* W2      = (const float*)d_in[8];
    const float* b2      = (const float*)d_in[9];
    const float* W3      = (const float*)d_in[10];
    // d_in[11] = b3: softmax-invariant constant shift, intentionally unused.
    float* out = (float*)d_out;

    cudaFuncSetAttribute(small_multi_kernel,
                         cudaFuncAttributeMaxDynamicSharedMemorySize, SMEM_BYTES);
    cudaFuncSetAttribute(pair_mma_kernel,
                         cudaFuncAttributeMaxDynamicSharedMemorySize, SMEM_BYTES);

    // weights -> bf16x2 permuted (tiled transpose); pad b2/w3; reset flag
    prep_kernel<<<dim3(64, 4), 256>>>(W2, Ws, W1, b2, W3);
    // sentinel / span_part / know_part / sent_part in ONE launch
    small_multi_kernel<<<dim3(4, 8, 4), 256, SMEM_BYTES>>>(span, know, bs, b1);
    // fused h1 -> h2 -> score partials (bf16, packed-part A)
    pair_mma_kernel<<<dim3(4, 130), 256, SMEM_BYTES>>>(s2c);
    // softmax + features
    softmax_features_kernel<<<NSPAN, 256>>>(s2c, lengths, know, out);
}